// round 1
// baseline (speedup 1.0000x reference)
#include <cuda_runtime.h>
#include <math.h>

// Problem constants
#define BSZ   8192
#define DIN   1024
#define DH    1024
#define NH    4
#define HD    256
#define DP    1365
#define GN    4096          // 4 gates * 1024
#define PLANE (BSZ*DH)      // 8388608

// Scratch (static device globals — allocation-free rule)
__device__ float g_xnorm[(size_t)BSZ * DIN];
__device__ float g_gates[(size_t)BSZ * GN];
__device__ float g_htnorm[(size_t)BSZ * DH];
__device__ float g_act[(size_t)BSZ * DP];

// ---------------------------------------------------------------------------
// K1: LayerNorm over last dim (1024). One block per row, 256 thr * 4 elems.
// ---------------------------------------------------------------------------
__global__ __launch_bounds__(256) void ln_kernel(const float* __restrict__ x,
                                                 const float* __restrict__ w,
                                                 const float* __restrict__ b)
{
    int row = blockIdx.x;
    int tid = threadIdx.x;
    const float* xr = x + (size_t)row * DIN;
    float4 v = *(const float4*)(xr + tid * 4);
    float s  = v.x + v.y + v.z + v.w;
    float ss = v.x*v.x + v.y*v.y + v.z*v.z + v.w*v.w;

    __shared__ float red0[8], red1[8];
    unsigned lane = tid & 31, wid = tid >> 5;
    #pragma unroll
    for (int o = 16; o; o >>= 1) {
        s  += __shfl_down_sync(0xffffffffu, s,  o);
        ss += __shfl_down_sync(0xffffffffu, ss, o);
    }
    if (!lane) { red0[wid] = s; red1[wid] = ss; }
    __syncthreads();
    float S = 0.f, SS = 0.f;
    #pragma unroll
    for (int i = 0; i < 8; ++i) { S += red0[i]; SS += red1[i]; }
    float mean = S * (1.f / DIN);
    float var  = SS * (1.f / DIN) - mean * mean;
    float rstd = rsqrtf(var + 1e-5f);

    float4 wv = *(const float4*)(w + tid * 4);
    float4 bv = *(const float4*)(b + tid * 4);
    float4 o4;
    o4.x = (v.x - mean) * rstd * wv.x + bv.x;
    o4.y = (v.y - mean) * rstd * wv.y + bv.y;
    o4.z = (v.z - mean) * rstd * wv.z + bv.z;
    o4.w = (v.w - mean) * rstd * wv.w + bv.w;
    *(float4*)(g_xnorm + (size_t)row * DIN + tid * 4) = o4;
}

// ---------------------------------------------------------------------------
// K2: gates = x_ln @ W_g + b_g + blockdiag(h_prev @ R_g) + rb_g
// GEMM with extended K: 1024 (input proj) + 256 (per-head recurrence).
// BM=128, BN=64, BK=16, 256 threads, 8x4 per-thread tile.
// Output column = gate*1024 + head*256 + e. A 64-col tile never crosses a
// gate (1024%64==0) or head (256%64==0) boundary.
// ---------------------------------------------------------------------------
__global__ __launch_bounds__(256) void gates_kernel(
    const float* __restrict__ hp,
    const float* __restrict__ Wz, const float* __restrict__ Wi,
    const float* __restrict__ Wf, const float* __restrict__ Wo,
    const float* __restrict__ bz, const float* __restrict__ bi,
    const float* __restrict__ bf, const float* __restrict__ bo,
    const float* __restrict__ Rz, const float* __restrict__ Ri,
    const float* __restrict__ Rf, const float* __restrict__ Ro,
    const float* __restrict__ rbz, const float* __restrict__ rbi,
    const float* __restrict__ rbf, const float* __restrict__ rbo)
{
    __shared__ float As[16][128];
    __shared__ float Bs[16][64];

    int row0 = blockIdx.y * 128;
    int col0 = blockIdx.x * 64;
    int g    = col0 >> 10;        // gate 0..3
    int nloc = col0 & 1023;       // index within gate [0,1024)
    int head = nloc >> 8;         // head 0..3
    int e0   = nloc & 255;        // index within head

    const float* W  = (g == 0) ? Wz  : (g == 1) ? Wi  : (g == 2) ? Wf  : Wo;
    const float* R  = (g == 0) ? Rz  : (g == 1) ? Ri  : (g == 2) ? Rf  : Ro;
    const float* bb = (g == 0) ? bz  : (g == 1) ? bi  : (g == 2) ? bf  : bo;
    const float* rb = (g == 0) ? rbz : (g == 1) ? rbi : (g == 2) ? rbf : rbo;

    int tid = threadIdx.x;
    int tx = tid & 15, ty = tid >> 4;
    float acc[8][4];
    #pragma unroll
    for (int i = 0; i < 8; ++i)
        #pragma unroll
        for (int j = 0; j < 4; ++j) acc[i][j] = 0.f;

    for (int kt = 0; kt < 80; ++kt) {          // 64 input-proj tiles + 16 recurrence tiles
        const float* Aptr;
        const float* Bptr;
        int bstride;
        if (kt < 64) {
            Aptr = g_xnorm + (size_t)row0 * DIN + kt * 16;       // [m*1024 + k]
            Bptr = W + (size_t)(kt * 16) * DH + nloc;            // [k*1024 + n]
            bstride = DH;
        } else {
            int k2 = (kt - 64) * 16;
            Aptr = hp + (size_t)row0 * DH + head * 256 + k2;     // [m*1024 + k]
            Bptr = R + head * 65536 + k2 * 256 + e0;             // [k*256 + n]
            bstride = 256;
        }
        __syncthreads();
        // A: 2 float4 per thread -> As[k][m] (transposed)
        #pragma unroll
        for (int j = 0; j < 2; ++j) {
            int q = tid * 2 + j;
            int m = q >> 2, kq = (q & 3) * 4;
            float4 v = *(const float4*)(Aptr + (size_t)m * DH + kq);
            As[kq + 0][m] = v.x; As[kq + 1][m] = v.y;
            As[kq + 2][m] = v.z; As[kq + 3][m] = v.w;
        }
        // B: 1 float4 per thread
        {
            int k = tid >> 4, n = (tid & 15) * 4;
            *(float4*)&Bs[k][n] = *(const float4*)(Bptr + (size_t)k * bstride + n);
        }
        __syncthreads();
        #pragma unroll
        for (int kk = 0; kk < 16; ++kk) {
            float4 a0 = *(const float4*)&As[kk][ty * 8];
            float4 a1 = *(const float4*)&As[kk][ty * 8 + 4];
            float4 b4 = *(const float4*)&Bs[kk][tx * 4];
            float av[8] = {a0.x, a0.y, a0.z, a0.w, a1.x, a1.y, a1.z, a1.w};
            float bv[4] = {b4.x, b4.y, b4.z, b4.w};
            #pragma unroll
            for (int i = 0; i < 8; ++i)
                #pragma unroll
                for (int j = 0; j < 4; ++j)
                    acc[i][j] = fmaf(av[i], bv[j], acc[i][j]);
        }
    }
    #pragma unroll
    for (int i = 0; i < 8; ++i) {
        int r = row0 + ty * 8 + i;
        #pragma unroll
        for (int j = 0; j < 4; ++j) {
            int c  = tx * 4 + j;
            int cg = nloc + c;   // D_H index within gate for biases
            g_gates[(size_t)r * GN + col0 + c] = acc[i][j] + bb[cg] + rb[cg];
        }
    }
}

// ---------------------------------------------------------------------------
// K3: sLSTM cell + per-head GroupNorm. One block per (b, head), 256 threads.
// Writes ht/ct/nt/mt output planes + g_htnorm.
// ---------------------------------------------------------------------------
__global__ __launch_bounds__(256) void cell_kernel(
    const float* __restrict__ cp, const float* __restrict__ np,
    const float* __restrict__ mp,
    const float* __restrict__ gnw, const float* __restrict__ gnb,
    float* __restrict__ ht_o, float* __restrict__ ct_o,
    float* __restrict__ nt_o, float* __restrict__ mt_o)
{
    int bh = blockIdx.x;
    int b = bh >> 2, h = bh & 3;
    int d = threadIdx.x;
    size_t idx   = (size_t)b * DH + h * 256 + d;
    size_t gbase = (size_t)b * GN + h * 256 + d;

    float z  = g_gates[gbase];
    float i_ = g_gates[gbase + 1024];
    float f_ = g_gates[gbase + 2048];
    float o_ = g_gates[gbase + 3072];
    float mpv = mp[idx], cpv = cp[idx], npv = np[idx];

    float zt = tanhf(z);
    float ot = 1.f / (1.f + expf(-o_));
    float fm = f_ + mpv;
    float mt = fmaxf(fm, i_);
    float it = expf(i_ - mt);
    float ft = expf(fm - mt);
    float ct = ft * cpv + it * zt;
    float nt = ft * npv + it;
    float ht = ot * (ct / (nt + 1e-13f));

    ht_o[idx] = ht; ct_o[idx] = ct; nt_o[idx] = nt; mt_o[idx] = mt;

    // GroupNorm over the 256 dims of this head
    float s = ht, ss = ht * ht;
    __shared__ float red0[8], red1[8];
    unsigned lane = d & 31, wid = d >> 5;
    #pragma unroll
    for (int o = 16; o; o >>= 1) {
        s  += __shfl_down_sync(0xffffffffu, s,  o);
        ss += __shfl_down_sync(0xffffffffu, ss, o);
    }
    if (!lane) { red0[wid] = s; red1[wid] = ss; }
    __syncthreads();
    float S = 0.f, SS = 0.f;
    #pragma unroll
    for (int i = 0; i < 8; ++i) { S += red0[i]; SS += red1[i]; }
    float mean = S * (1.f / 256.f);
    float var  = SS * (1.f / 256.f) - mean * mean;
    float rstd = rsqrtf(var + 1e-5f);
    int c = h * 256 + d;
    g_htnorm[idx] = (ht - mean) * rstd * gnw[c] + gnb[c];
}

// ---------------------------------------------------------------------------
// K4: up-projection + GeGLU, fused. For act column c (< 1365) the block
// accumulates BOTH Wup[:,c] (s-part) and Wup[:,c+1365] (g-part) and writes
// act = s * gelu(g) directly (the 2*D_P "up" tensor is never materialized).
// BM=64, BN=64, BK=16, 256 threads, 4x4 per-thread tile, dual accumulators.
// ---------------------------------------------------------------------------
__global__ __launch_bounds__(256) void upact_kernel(const float* __restrict__ Wup,
                                                    const float* __restrict__ bup)
{
    __shared__ float As[16][64];
    __shared__ float Bss[16][64];
    __shared__ float Bgg[16][64];
    int row0 = blockIdx.y * 64;
    int col0 = blockIdx.x * 64;
    int tid = threadIdx.x;
    int tx = tid & 15, ty = tid >> 4;
    float accs[4][4], accg[4][4];
    #pragma unroll
    for (int i = 0; i < 4; ++i)
        #pragma unroll
        for (int j = 0; j < 4; ++j) { accs[i][j] = 0.f; accg[i][j] = 0.f; }

    for (int kt = 0; kt < 64; ++kt) {
        int k0 = kt * 16;
        __syncthreads();
        {   // A: 1 float4 per thread, transposed store
            int m = tid >> 2, kq = (tid & 3) * 4;
            float4 v = *(const float4*)(g_htnorm + (size_t)(row0 + m) * DH + k0 + kq);
            As[kq + 0][m] = v.x; As[kq + 1][m] = v.y;
            As[kq + 2][m] = v.z; As[kq + 3][m] = v.w;
        }
        // B: scalar loads (1365 offset breaks float4 alignment), 4 per thread per tile
        #pragma unroll
        for (int it = 0; it < 4; ++it) {
            int q = tid + 256 * it;
            int k = q >> 6, n = q & 63;
            int c = col0 + n;
            float vs = 0.f, vg = 0.f;
            if (c < DP) {
                const float* wrow = Wup + (size_t)(k0 + k) * (2 * DP);
                vs = wrow[c];
                vg = wrow[c + DP];
            }
            Bss[k][n] = vs;
            Bgg[k][n] = vg;
        }
        __syncthreads();
        #pragma unroll
        for (int kk = 0; kk < 16; ++kk) {
            float4 a4 = *(const float4*)&As[kk][ty * 4];
            float4 b1 = *(const float4*)&Bss[kk][tx * 4];
            float4 b2 = *(const float4*)&Bgg[kk][tx * 4];
            float av[4] = {a4.x, a4.y, a4.z, a4.w};
            float s1[4] = {b1.x, b1.y, b1.z, b1.w};
            float s2[4] = {b2.x, b2.y, b2.z, b2.w};
            #pragma unroll
            for (int i = 0; i < 4; ++i)
                #pragma unroll
                for (int j = 0; j < 4; ++j) {
                    accs[i][j] = fmaf(av[i], s1[j], accs[i][j]);
                    accg[i][j] = fmaf(av[i], s2[j], accg[i][j]);
                }
        }
    }
    #pragma unroll
    for (int i = 0; i < 4; ++i) {
        int r = row0 + ty * 4 + i;
        #pragma unroll
        for (int j = 0; j < 4; ++j) {
            int c = col0 + tx * 4 + j;
            if (c < DP) {
                float sv = accs[i][j] + bup[c];
                float gv = accg[i][j] + bup[c + DP];
                float ge = 0.5f * gv * (1.f + erff(gv * 0.70710678118654752f));
                g_act[(size_t)r * DP + c] = sv * ge;
            }
        }
    }
}

// ---------------------------------------------------------------------------
// K5: y = act @ Wdown + bdown + x  (K = 1365, partial last K-tile)
// BM=128, BN=64, BK=16, 256 threads, 8x4 per-thread tile.
// ---------------------------------------------------------------------------
__global__ __launch_bounds__(256) void down_kernel(const float* __restrict__ x,
                                                   const float* __restrict__ Wd,
                                                   const float* __restrict__ bd,
                                                   float* __restrict__ y)
{
    __shared__ float As[16][128];
    __shared__ float Bs[16][64];
    int row0 = blockIdx.y * 128;
    int col0 = blockIdx.x * 64;
    int tid = threadIdx.x;
    int tx = tid & 15, ty = tid >> 4;
    float acc[8][4];
    #pragma unroll
    for (int i = 0; i < 8; ++i)
        #pragma unroll
        for (int j = 0; j < 4; ++j) acc[i][j] = 0.f;

    for (int kt = 0; kt < 86; ++kt) {          // ceil(1365/16)
        int k0 = kt * 16;
        __syncthreads();
        {   // A: g_act rows stride 1365 (unaligned) -> scalar loads, 8/thread
            int m  = tid >> 1;
            int kb = (tid & 1) * 8;
            const float* ap = g_act + (size_t)(row0 + m) * DP;
            #pragma unroll
            for (int i = 0; i < 8; ++i) {
                int k = k0 + kb + i;
                As[kb + i][m] = (k < DP) ? ap[k] : 0.f;
            }
        }
        #pragma unroll
        for (int it = 0; it < 4; ++it) {
            int q = tid + 256 * it;
            int k = q >> 6, n = q & 63;
            int kk2 = k0 + k;
            Bs[k][n] = (kk2 < DP) ? Wd[(size_t)kk2 * DIN + col0 + n] : 0.f;
        }
        __syncthreads();
        #pragma unroll
        for (int kk = 0; kk < 16; ++kk) {
            float4 a0 = *(const float4*)&As[kk][ty * 8];
            float4 a1 = *(const float4*)&As[kk][ty * 8 + 4];
            float4 b4 = *(const float4*)&Bs[kk][tx * 4];
            float av[8] = {a0.x, a0.y, a0.z, a0.w, a1.x, a1.y, a1.z, a1.w};
            float bv[4] = {b4.x, b4.y, b4.z, b4.w};
            #pragma unroll
            for (int i = 0; i < 8; ++i)
                #pragma unroll
                for (int j = 0; j < 4; ++j)
                    acc[i][j] = fmaf(av[i], bv[j], acc[i][j]);
        }
    }
    #pragma unroll
    for (int i = 0; i < 8; ++i) {
        int r = row0 + ty * 8 + i;
        #pragma unroll
        for (int j = 0; j < 4; ++j) {
            int c = col0 + tx * 4 + j;
            y[(size_t)r * DIN + c] = acc[i][j] + bd[c] + x[(size_t)r * DIN + c];
        }
    }
}

// ---------------------------------------------------------------------------
extern "C" void kernel_launch(void* const* d_in, const int* in_sizes, int n_in,
                              void* d_out, int out_size)
{
    const float* x      = (const float*)d_in[0];
    const float* h_prev = (const float*)d_in[1];
    const float* c_prev = (const float*)d_in[2];
    const float* n_prev = (const float*)d_in[3];
    const float* m_prev = (const float*)d_in[4];
    const float* ln_w   = (const float*)d_in[5];
    const float* ln_b   = (const float*)d_in[6];
    const float* Wz = (const float*)d_in[7];
    const float* bz = (const float*)d_in[8];
    const float* Wi = (const float*)d_in[9];
    const float* bi = (const float*)d_in[10];
    const float* Wf = (const float*)d_in[11];
    const float* bf = (const float*)d_in[12];
    const float* Wo = (const float*)d_in[13];
    const float* bo = (const float*)d_in[14];
    const float* Rz  = (const float*)d_in[15];
    const float* rbz = (const float*)d_in[16];
    const float* Ri  = (const float*)d_in[17];
    const float* rbi = (const float*)d_in[18];
    const float* Rf  = (const float*)d_in[19];
    const float* rbf = (const float*)d_in[20];
    const float* Ro  = (const float*)d_in[21];
    const float* rbo = (const float*)d_in[22];
    const float* gn_w = (const float*)d_in[23];
    const float* gn_b = (const float*)d_in[24];
    const float* Wup  = (const float*)d_in[25];
    const float* bup  = (const float*)d_in[26];
    const float* Wdown = (const float*)d_in[27];
    const float* bdown = (const float*)d_in[28];

    float* out  = (float*)d_out;
    float* y_o  = out;
    float* ht_o = out + (size_t)PLANE;
    float* ct_o = out + (size_t)2 * PLANE;
    float* nt_o = out + (size_t)3 * PLANE;
    float* mt_o = out + (size_t)4 * PLANE;

    ln_kernel<<<BSZ, 256>>>(x, ln_w, ln_b);

    gates_kernel<<<dim3(GN / 64, BSZ / 128), 256>>>(
        h_prev, Wz, Wi, Wf, Wo, bz, bi, bf, bo,
        Rz, Ri, Rf, Ro, rbz, rbi, rbf, rbo);

    cell_kernel<<<BSZ * NH, 256>>>(c_prev, n_prev, m_prev, gn_w, gn_b,
                                   ht_o, ct_o, nt_o, mt_o);

    upact_kernel<<<dim3((DP + 63) / 64, BSZ / 64), 256>>>(Wup, bup);

    down_kernel<<<dim3(DIN / 64, BSZ / 128), 256>>>(x, Wdown, bdown, y_o);
}

// round 2
// speedup vs baseline: 2.7476x; 2.7476x over previous
#include <cuda_runtime.h>
#include <math.h>

// Problem constants
#define BSZ   8192
#define DIN   1024
#define DH    1024
#define NH    4
#define HD    256
#define DP    1365
#define DPAD  1376          // DP padded to multiple of 16 (and 16B-aligned rows)
#define NPAD  1408          // DP padded to multiple of 64 (N-tile size)
#define GN    4096
#define PLANE (BSZ*DH)

// Scratch (static device globals — allocation-free rule)
__device__ float g_xnorm[(size_t)BSZ * DIN];
__device__ float g_gates[(size_t)BSZ * GN];
__device__ float g_htnorm[(size_t)BSZ * DH];
__device__ float g_act[(size_t)BSZ * DPAD];
__device__ float g_WupS[(size_t)DIN * NPAD];
__device__ float g_WupG[(size_t)DIN * NPAD];
__device__ float g_Wd[(size_t)DPAD * DIN];

// ---------------------------------------------------------------------------
// helpers
// ---------------------------------------------------------------------------
__device__ __forceinline__ float tf32r(float x) {
    unsigned u;
    asm("cvt.rna.tf32.f32 %0, %1;" : "=r"(u) : "f"(x));
    return __uint_as_float(u);
}
__device__ __forceinline__ float4 tf32r4(float4 v) {
    v.x = tf32r(v.x); v.y = tf32r(v.y); v.z = tf32r(v.z); v.w = tf32r(v.w);
    return v;
}
__device__ __forceinline__ void mma8(float* c, const unsigned* a, const unsigned* b) {
    asm volatile(
        "mma.sync.aligned.m16n8k8.row.col.f32.tf32.tf32.f32 "
        "{%0,%1,%2,%3}, {%4,%5,%6,%7}, {%8,%9}, {%0,%1,%2,%3};"
        : "+f"(c[0]), "+f"(c[1]), "+f"(c[2]), "+f"(c[3])
        : "r"(a[0]), "r"(a[1]), "r"(a[2]), "r"(a[3]), "r"(b[0]), "r"(b[1]));
}

// ---------------------------------------------------------------------------
// K0a: repack Wup into s-half / g-half, zero-padded to NPAD cols
// ---------------------------------------------------------------------------
__global__ __launch_bounds__(256) void repack_wup(const float* __restrict__ Wup)
{
    int idx = blockIdx.x * 256 + threadIdx.x;
    if (idx >= DIN * NPAD) return;
    int k = idx / NPAD, c = idx % NPAD;
    float s = 0.f, g = 0.f;
    if (c < DP) {
        const float* row = Wup + (size_t)k * (2 * DP);
        s = row[c];
        g = row[c + DP];
    }
    g_WupS[idx] = s;
    g_WupG[idx] = g;
}

// K0b: repack Wdown with zero rows up to DPAD
__global__ __launch_bounds__(256) void repack_wd(const float* __restrict__ Wd)
{
    int idx = blockIdx.x * 256 + threadIdx.x;
    if (idx >= DPAD * DIN) return;
    int k = idx >> 10, n = idx & 1023;
    g_Wd[idx] = (k < DP) ? Wd[(size_t)k * DIN + n] : 0.f;
}

// ---------------------------------------------------------------------------
// K1: LayerNorm over last dim (1024). One block per row, 256 thr * 4 elems.
// ---------------------------------------------------------------------------
__global__ __launch_bounds__(256) void ln_kernel(const float* __restrict__ x,
                                                 const float* __restrict__ w,
                                                 const float* __restrict__ b)
{
    int row = blockIdx.x;
    int tid = threadIdx.x;
    const float* xr = x + (size_t)row * DIN;
    float4 v = *(const float4*)(xr + tid * 4);
    float s  = v.x + v.y + v.z + v.w;
    float ss = v.x*v.x + v.y*v.y + v.z*v.z + v.w*v.w;

    __shared__ float red0[8], red1[8];
    unsigned lane = tid & 31, wid = tid >> 5;
    #pragma unroll
    for (int o = 16; o; o >>= 1) {
        s  += __shfl_down_sync(0xffffffffu, s,  o);
        ss += __shfl_down_sync(0xffffffffu, ss, o);
    }
    if (!lane) { red0[wid] = s; red1[wid] = ss; }
    __syncthreads();
    float S = 0.f, SS = 0.f;
    #pragma unroll
    for (int i = 0; i < 8; ++i) { S += red0[i]; SS += red1[i]; }
    float mean = S * (1.f / DIN);
    float var  = SS * (1.f / DIN) - mean * mean;
    float rstd = rsqrtf(var + 1e-5f);

    float4 wv = *(const float4*)(w + tid * 4);
    float4 bv = *(const float4*)(b + tid * 4);
    float4 o4;
    o4.x = (v.x - mean) * rstd * wv.x + bv.x;
    o4.y = (v.y - mean) * rstd * wv.y + bv.y;
    o4.z = (v.z - mean) * rstd * wv.z + bv.z;
    o4.w = (v.w - mean) * rstd * wv.w + bv.w;
    *(float4*)(g_xnorm + (size_t)row * DIN + tid * 4) = o4;
}

// ---------------------------------------------------------------------------
// K2: gates = x_ln @ W_g + b_g + blockdiag(h_prev @ R_g) + rb_g   (tf32 mma)
// BM=128, BN=128, BK=16 (extended K: 64 input tiles + 16 recurrence tiles).
// 8 warps (4m x 2n), warp tile 32x64, m16n8k8 tf32.
// ---------------------------------------------------------------------------
#define SA 20
#define SB 136
__global__ __launch_bounds__(256) void gates_mma(
    const float* __restrict__ hp,
    const float* __restrict__ Wz, const float* __restrict__ Wi,
    const float* __restrict__ Wf, const float* __restrict__ Wo,
    const float* __restrict__ bz, const float* __restrict__ bi,
    const float* __restrict__ bf, const float* __restrict__ bo,
    const float* __restrict__ Rz, const float* __restrict__ Ri,
    const float* __restrict__ Rf, const float* __restrict__ Ro,
    const float* __restrict__ rbz, const float* __restrict__ rbi,
    const float* __restrict__ rbf, const float* __restrict__ rbo)
{
    __shared__ float As[2][128 * SA];
    __shared__ float Bs[2][16 * SB];

    const int row0 = blockIdx.y * 128;
    const int col0 = blockIdx.x * 128;
    const int g    = col0 >> 10;
    const int nloc = col0 & 1023;
    const int head = nloc >> 8;
    const int e0   = nloc & 255;

    const float* W  = (g == 0) ? Wz  : (g == 1) ? Wi  : (g == 2) ? Wf  : Wo;
    const float* R  = (g == 0) ? Rz  : (g == 1) ? Ri  : (g == 2) ? Rf  : Ro;
    const float* bb = (g == 0) ? bz  : (g == 1) ? bi  : (g == 2) ? bf  : bo;
    const float* rb = (g == 0) ? rbz : (g == 1) ? rbi : (g == 2) ? rbf : rbo;

    const int tid  = threadIdx.x;
    const int lane = tid & 31, wid = tid >> 5;
    const int wm = wid & 3, wn = wid >> 2;
    const int grp = lane >> 2, tig = lane & 3;

    const int am0 = tid >> 2;
    const int ak  = (tid & 3) * 4;
    const int bk0 = tid >> 5;
    const int bn  = (tid & 31) * 4;

    float4 pa[2], pb[2];

    auto LOADT = [&](int kt) {
        if (kt < 64) {
            const float* Ap = g_xnorm + (size_t)row0 * DIN + kt * 16;
            const float* Bp = W + (size_t)(kt * 16) * DH + nloc;
            pa[0] = *(const float4*)(Ap + (size_t)am0 * DIN + ak);
            pa[1] = *(const float4*)(Ap + (size_t)(am0 + 64) * DIN + ak);
            pb[0] = *(const float4*)(Bp + (size_t)bk0 * DH + bn);
            pb[1] = *(const float4*)(Bp + (size_t)(bk0 + 8) * DH + bn);
        } else {
            int k2 = (kt - 64) * 16;
            const float* Ap = hp + (size_t)row0 * DH + head * 256 + k2;
            const float* Bp = R + head * 65536 + (size_t)k2 * 256 + e0;
            pa[0] = *(const float4*)(Ap + (size_t)am0 * DH + ak);
            pa[1] = *(const float4*)(Ap + (size_t)(am0 + 64) * DH + ak);
            pb[0] = *(const float4*)(Bp + (size_t)bk0 * 256 + bn);
            pb[1] = *(const float4*)(Bp + (size_t)(bk0 + 8) * 256 + bn);
        }
    };
    auto STORET = [&](int buf) {
        float* A = As[buf]; float* B = Bs[buf];
        *(float4*)&A[am0 * SA + ak]        = tf32r4(pa[0]);
        *(float4*)&A[(am0 + 64) * SA + ak] = tf32r4(pa[1]);
        *(float4*)&B[bk0 * SB + bn]        = tf32r4(pb[0]);
        *(float4*)&B[(bk0 + 8) * SB + bn]  = tf32r4(pb[1]);
    };

    float acc[2][8][4];
    #pragma unroll
    for (int mi = 0; mi < 2; ++mi)
        #pragma unroll
        for (int ni = 0; ni < 8; ++ni)
            #pragma unroll
            for (int q = 0; q < 4; ++q) acc[mi][ni][q] = 0.f;

    LOADT(0); STORET(0); __syncthreads();

    for (int kt = 0; kt < 80; ++kt) {
        const int cur = kt & 1;
        if (kt < 79) LOADT(kt + 1);
        const float* A = As[cur]; const float* B = Bs[cur];
        #pragma unroll
        for (int ks = 0; ks < 2; ++ks) {
            const int kk = ks * 8;
            unsigned af[2][4], bf4[8][2];
            #pragma unroll
            for (int mi = 0; mi < 2; ++mi) {
                int r = wm * 32 + mi * 16 + grp;
                af[mi][0] = __float_as_uint(A[r * SA + kk + tig]);
                af[mi][1] = __float_as_uint(A[(r + 8) * SA + kk + tig]);
                af[mi][2] = __float_as_uint(A[r * SA + kk + tig + 4]);
                af[mi][3] = __float_as_uint(A[(r + 8) * SA + kk + tig + 4]);
            }
            #pragma unroll
            for (int ni = 0; ni < 8; ++ni) {
                int c = wn * 64 + ni * 8 + grp;
                bf4[ni][0] = __float_as_uint(B[(kk + tig) * SB + c]);
                bf4[ni][1] = __float_as_uint(B[(kk + tig + 4) * SB + c]);
            }
            #pragma unroll
            for (int mi = 0; mi < 2; ++mi)
                #pragma unroll
                for (int ni = 0; ni < 8; ++ni)
                    mma8(acc[mi][ni], af[mi], bf4[ni]);
        }
        if (kt < 79) { STORET((kt + 1) & 1); __syncthreads(); }
    }

    #pragma unroll
    for (int mi = 0; mi < 2; ++mi) {
        int r = row0 + wm * 32 + mi * 16 + grp;
        #pragma unroll
        for (int ni = 0; ni < 8; ++ni) {
            int c  = col0 + wn * 64 + ni * 8 + tig * 2;
            int cg = c & 1023;
            float b0 = bb[cg] + rb[cg];
            float b1 = bb[cg + 1] + rb[cg + 1];
            float2 v0 = {acc[mi][ni][0] + b0, acc[mi][ni][1] + b1};
            float2 v1 = {acc[mi][ni][2] + b0, acc[mi][ni][3] + b1};
            *(float2*)&g_gates[(size_t)r * GN + c]       = v0;
            *(float2*)&g_gates[(size_t)(r + 8) * GN + c] = v1;
        }
    }
}

// ---------------------------------------------------------------------------
// K3: sLSTM cell + per-head GroupNorm. One block per (b, head), 256 threads.
// ---------------------------------------------------------------------------
__global__ __launch_bounds__(256) void cell_kernel(
    const float* __restrict__ cp, const float* __restrict__ np,
    const float* __restrict__ mp,
    const float* __restrict__ gnw, const float* __restrict__ gnb,
    float* __restrict__ ht_o, float* __restrict__ ct_o,
    float* __restrict__ nt_o, float* __restrict__ mt_o)
{
    int bh = blockIdx.x;
    int b = bh >> 2, h = bh & 3;
    int d = threadIdx.x;
    size_t idx   = (size_t)b * DH + h * 256 + d;
    size_t gbase = (size_t)b * GN + h * 256 + d;

    float z  = g_gates[gbase];
    float i_ = g_gates[gbase + 1024];
    float f_ = g_gates[gbase + 2048];
    float o_ = g_gates[gbase + 3072];
    float mpv = mp[idx], cpv = cp[idx], npv = np[idx];

    float zt = tanhf(z);
    float ot = 1.f / (1.f + expf(-o_));
    float fm = f_ + mpv;
    float mt = fmaxf(fm, i_);
    float it = expf(i_ - mt);
    float ft = expf(fm - mt);
    float ct = ft * cpv + it * zt;
    float nt = ft * npv + it;
    float ht = ot * (ct / (nt + 1e-13f));

    ht_o[idx] = ht; ct_o[idx] = ct; nt_o[idx] = nt; mt_o[idx] = mt;

    float s = ht, ss = ht * ht;
    __shared__ float red0[8], red1[8];
    unsigned lane = d & 31, wid = d >> 5;
    #pragma unroll
    for (int o = 16; o; o >>= 1) {
        s  += __shfl_down_sync(0xffffffffu, s,  o);
        ss += __shfl_down_sync(0xffffffffu, ss, o);
    }
    if (!lane) { red0[wid] = s; red1[wid] = ss; }
    __syncthreads();
    float S = 0.f, SS = 0.f;
    #pragma unroll
    for (int i = 0; i < 8; ++i) { S += red0[i]; SS += red1[i]; }
    float mean = S * (1.f / 256.f);
    float var  = SS * (1.f / 256.f) - mean * mean;
    float rstd = rsqrtf(var + 1e-5f);
    int c = h * 256 + d;
    g_htnorm[idx] = (ht - mean) * rstd * gnw[c] + gnb[c];
}

// ---------------------------------------------------------------------------
// K4: up-projection + GeGLU, tf32 mma, dual-B (s and g halves).
// BM=128, BN=64, BK=16, 8 warps (4m x 2n), warp tile 32x32.
// N tiles run over NPAD=1408 (zero-padded weights).
// ---------------------------------------------------------------------------
#define SBU 72
__global__ __launch_bounds__(256) void upact_mma(const float* __restrict__ bup)
{
    __shared__ float As[2][128 * SA];
    __shared__ float BsS[2][16 * SBU];
    __shared__ float BsG[2][16 * SBU];

    const int row0 = blockIdx.y * 128;
    const int col0 = blockIdx.x * 64;

    const int tid  = threadIdx.x;
    const int lane = tid & 31, wid = tid >> 5;
    const int wm = wid & 3, wn = wid >> 2;
    const int grp = lane >> 2, tig = lane & 3;

    const int am0 = tid >> 2;
    const int ak  = (tid & 3) * 4;
    const int bk  = tid >> 4;
    const int bn  = (tid & 15) * 4;

    float4 pa[2], pbS, pbG;

    auto LOADT = [&](int kt) {
        const float* Ap = g_htnorm + (size_t)row0 * DH + kt * 16;
        pa[0] = *(const float4*)(Ap + (size_t)am0 * DH + ak);
        pa[1] = *(const float4*)(Ap + (size_t)(am0 + 64) * DH + ak);
        size_t boff = (size_t)(kt * 16 + bk) * NPAD + col0 + bn;
        pbS = *(const float4*)(g_WupS + boff);
        pbG = *(const float4*)(g_WupG + boff);
    };
    auto STORET = [&](int buf) {
        float* A = As[buf];
        *(float4*)&A[am0 * SA + ak]        = tf32r4(pa[0]);
        *(float4*)&A[(am0 + 64) * SA + ak] = tf32r4(pa[1]);
        *(float4*)&BsS[buf][bk * SBU + bn] = tf32r4(pbS);
        *(float4*)&BsG[buf][bk * SBU + bn] = tf32r4(pbG);
    };

    float accS[2][4][4], accG[2][4][4];
    #pragma unroll
    for (int mi = 0; mi < 2; ++mi)
        #pragma unroll
        for (int ni = 0; ni < 4; ++ni)
            #pragma unroll
            for (int q = 0; q < 4; ++q) { accS[mi][ni][q] = 0.f; accG[mi][ni][q] = 0.f; }

    LOADT(0); STORET(0); __syncthreads();

    for (int kt = 0; kt < 64; ++kt) {
        const int cur = kt & 1;
        if (kt < 63) LOADT(kt + 1);
        const float* A = As[cur];
        const float* BS = BsS[cur];
        const float* BG = BsG[cur];
        #pragma unroll
        for (int ks = 0; ks < 2; ++ks) {
            const int kk = ks * 8;
            unsigned af[2][4], bs[4][2], bg[4][2];
            #pragma unroll
            for (int mi = 0; mi < 2; ++mi) {
                int r = wm * 32 + mi * 16 + grp;
                af[mi][0] = __float_as_uint(A[r * SA + kk + tig]);
                af[mi][1] = __float_as_uint(A[(r + 8) * SA + kk + tig]);
                af[mi][2] = __float_as_uint(A[r * SA + kk + tig + 4]);
                af[mi][3] = __float_as_uint(A[(r + 8) * SA + kk + tig + 4]);
            }
            #pragma unroll
            for (int ni = 0; ni < 4; ++ni) {
                int c = wn * 32 + ni * 8 + grp;
                bs[ni][0] = __float_as_uint(BS[(kk + tig) * SBU + c]);
                bs[ni][1] = __float_as_uint(BS[(kk + tig + 4) * SBU + c]);
                bg[ni][0] = __float_as_uint(BG[(kk + tig) * SBU + c]);
                bg[ni][1] = __float_as_uint(BG[(kk + tig + 4) * SBU + c]);
            }
            #pragma unroll
            for (int mi = 0; mi < 2; ++mi)
                #pragma unroll
                for (int ni = 0; ni < 4; ++ni) {
                    mma8(accS[mi][ni], af[mi], bs[ni]);
                    mma8(accG[mi][ni], af[mi], bg[ni]);
                }
        }
        if (kt < 63) { STORET((kt + 1) & 1); __syncthreads(); }
    }

    #pragma unroll
    for (int mi = 0; mi < 2; ++mi) {
        int r = row0 + wm * 32 + mi * 16 + grp;
        #pragma unroll
        for (int ni = 0; ni < 4; ++ni) {
            int c = col0 + wn * 32 + ni * 8 + tig * 2;
            #pragma unroll
            for (int half = 0; half < 2; ++half) {
                int rr = r + half * 8;
                #pragma unroll
                for (int j = 0; j < 2; ++j) {
                    int cc = c + j;
                    if (cc < DPAD) {
                        float v = 0.f;
                        if (cc < DP) {
                            float sv = accS[mi][ni][half * 2 + j] + bup[cc];
                            float gv = accG[mi][ni][half * 2 + j] + bup[cc + DP];
                            float ge = 0.5f * gv * (1.f + erff(gv * 0.70710678118654752f));
                            v = sv * ge;
                        }
                        g_act[(size_t)rr * DPAD + cc] = v;
                    }
                }
            }
        }
    }
}

// ---------------------------------------------------------------------------
// K5: y = act @ Wdown + bdown + x   (tf32 mma, K padded to 1376)
// BM=128, BN=128, BK=16, 86 K tiles (zero-padded A cols + B rows).
// ---------------------------------------------------------------------------
__global__ __launch_bounds__(256) void down_mma(const float* __restrict__ x,
                                                const float* __restrict__ bd,
                                                float* __restrict__ y)
{
    __shared__ float As[2][128 * SA];
    __shared__ float Bs[2][16 * SB];

    const int row0 = blockIdx.y * 128;
    const int col0 = blockIdx.x * 128;

    const int tid  = threadIdx.x;
    const int lane = tid & 31, wid = tid >> 5;
    const int wm = wid & 3, wn = wid >> 2;
    const int grp = lane >> 2, tig = lane & 3;

    const int am0 = tid >> 2;
    const int ak  = (tid & 3) * 4;
    const int bk0 = tid >> 5;
    const int bn  = (tid & 31) * 4;

    float4 pa[2], pb[2];

    auto LOADT = [&](int kt) {
        const float* Ap = g_act + (size_t)row0 * DPAD + kt * 16;
        pa[0] = *(const float4*)(Ap + (size_t)am0 * DPAD + ak);
        pa[1] = *(const float4*)(Ap + (size_t)(am0 + 64) * DPAD + ak);
        const float* Bp = g_Wd + (size_t)(kt * 16) * DIN + col0;
        pb[0] = *(const float4*)(Bp + (size_t)bk0 * DIN + bn);
        pb[1] = *(const float4*)(Bp + (size_t)(bk0 + 8) * DIN + bn);
    };
    auto STORET = [&](int buf) {
        float* A = As[buf]; float* B = Bs[buf];
        *(float4*)&A[am0 * SA + ak]        = tf32r4(pa[0]);
        *(float4*)&A[(am0 + 64) * SA + ak] = tf32r4(pa[1]);
        *(float4*)&B[bk0 * SB + bn]        = tf32r4(pb[0]);
        *(float4*)&B[(bk0 + 8) * SB + bn]  = tf32r4(pb[1]);
    };

    float acc[2][8][4];
    #pragma unroll
    for (int mi = 0; mi < 2; ++mi)
        #pragma unroll
        for (int ni = 0; ni < 8; ++ni)
            #pragma unroll
            for (int q = 0; q < 4; ++q) acc[mi][ni][q] = 0.f;

    LOADT(0); STORET(0); __syncthreads();

    const int NT = DPAD / 16;  // 86
    for (int kt = 0; kt < NT; ++kt) {
        const int cur = kt & 1;
        if (kt < NT - 1) LOADT(kt + 1);
        const float* A = As[cur]; const float* B = Bs[cur];
        #pragma unroll
        for (int ks = 0; ks < 2; ++ks) {
            const int kk = ks * 8;
            unsigned af[2][4], bf4[8][2];
            #pragma unroll
            for (int mi = 0; mi < 2; ++mi) {
                int r = wm * 32 + mi * 16 + grp;
                af[mi][0] = __float_as_uint(A[r * SA + kk + tig]);
                af[mi][1] = __float_as_uint(A[(r + 8) * SA + kk + tig]);
                af[mi][2] = __float_as_uint(A[r * SA + kk + tig + 4]);
                af[mi][3] = __float_as_uint(A[(r + 8) * SA + kk + tig + 4]);
            }
            #pragma unroll
            for (int ni = 0; ni < 8; ++ni) {
                int c = wn * 64 + ni * 8 + grp;
                bf4[ni][0] = __float_as_uint(B[(kk + tig) * SB + c]);
                bf4[ni][1] = __float_as_uint(B[(kk + tig + 4) * SB + c]);
            }
            #pragma unroll
            for (int mi = 0; mi < 2; ++mi)
                #pragma unroll
                for (int ni = 0; ni < 8; ++ni)
                    mma8(acc[mi][ni], af[mi], bf4[ni]);
        }
        if (kt < NT - 1) { STORET((kt + 1) & 1); __syncthreads(); }
    }

    #pragma unroll
    for (int mi = 0; mi < 2; ++mi) {
        int r = row0 + wm * 32 + mi * 16 + grp;
        #pragma unroll
        for (int ni = 0; ni < 8; ++ni) {
            int c = col0 + wn * 64 + ni * 8 + tig * 2;
            float b0 = bd[c], b1 = bd[c + 1];
            float2 x0 = *(const float2*)&x[(size_t)r * DIN + c];
            float2 x1 = *(const float2*)&x[(size_t)(r + 8) * DIN + c];
            float2 v0 = {acc[mi][ni][0] + b0 + x0.x, acc[mi][ni][1] + b1 + x0.y};
            float2 v1 = {acc[mi][ni][2] + b0 + x1.x, acc[mi][ni][3] + b1 + x1.y};
            *(float2*)&y[(size_t)r * DIN + c]       = v0;
            *(float2*)&y[(size_t)(r + 8) * DIN + c] = v1;
        }
    }
}

// ---------------------------------------------------------------------------
extern "C" void kernel_launch(void* const* d_in, const int* in_sizes, int n_in,
                              void* d_out, int out_size)
{
    const float* x      = (const float*)d_in[0];
    const float* h_prev = (const float*)d_in[1];
    const float* c_prev = (const float*)d_in[2];
    const float* n_prev = (const float*)d_in[3];
    const float* m_prev = (const float*)d_in[4];
    const float* ln_w   = (const float*)d_in[5];
    const float* ln_b   = (const float*)d_in[6];
    const float* Wz = (const float*)d_in[7];
    const float* bz = (const float*)d_in[8];
    const float* Wi = (const float*)d_in[9];
    const float* bi = (const float*)d_in[10];
    const float* Wf = (const float*)d_in[11];
    const float* bf = (const float*)d_in[12];
    const float* Wo = (const float*)d_in[13];
    const float* bo = (const float*)d_in[14];
    const float* Rz  = (const float*)d_in[15];
    const float* rbz = (const float*)d_in[16];
    const float* Ri  = (const float*)d_in[17];
    const float* rbi = (const float*)d_in[18];
    const float* Rf  = (const float*)d_in[19];
    const float* rbf = (const float*)d_in[20];
    const float* Ro  = (const float*)d_in[21];
    const float* rbo = (const float*)d_in[22];
    const float* gn_w = (const float*)d_in[23];
    const float* gn_b = (const float*)d_in[24];
    const float* Wup  = (const float*)d_in[25];
    const float* bup  = (const float*)d_in[26];
    const float* Wdown = (const float*)d_in[27];
    const float* bdown = (const float*)d_in[28];

    float* out  = (float*)d_out;
    float* y_o  = out;
    float* ht_o = out + (size_t)PLANE;
    float* ct_o = out + (size_t)2 * PLANE;
    float* nt_o = out + (size_t)3 * PLANE;
    float* mt_o = out + (size_t)4 * PLANE;

    repack_wup<<<(DIN * NPAD + 255) / 256, 256>>>(Wup);
    repack_wd<<<(DPAD * DIN + 255) / 256, 256>>>(Wdown);

    ln_kernel<<<BSZ, 256>>>(x, ln_w, ln_b);

    gates_mma<<<dim3(GN / 128, BSZ / 128), 256>>>(
        h_prev, Wz, Wi, Wf, Wo, bz, bi, bf, bo,
        Rz, Ri, Rf, Ro, rbz, rbi, rbf, rbo);

    cell_kernel<<<BSZ * NH, 256>>>(c_prev, n_prev, m_prev, gn_w, gn_b,
                                   ht_o, ct_o, nt_o, mt_o);

    upact_mma<<<dim3(NPAD / 64, BSZ / 128), 256>>>(bup);

    down_mma<<<dim3(DIN / 128, BSZ / 128), 256>>>(x, bdown, y_o);
}

// round 3
// speedup vs baseline: 3.0538x; 1.1115x over previous
#include <cuda_runtime.h>
#include <math.h>

// Problem constants
#define BSZ   8192
#define DIN   1024
#define DH    1024
#define NH    4
#define HD    256
#define DP    1365
#define DPAD  1376
#define NPAD  1408
#define GN    4096
#define PLANE (BSZ*DH)

#define SA  20
#define SB  136
#define SBU 72

// pipeline stage sizes (floats)
#define STG_G (128*SA + 16*SB)        // 4736
#define STG_U (128*SA + 2*16*SBU)     // 4864
#define NSTAGE 3

// Scratch (static device globals — allocation-free rule)
__device__ float g_xnorm[(size_t)BSZ * DIN];
__device__ float g_hr[(size_t)BSZ * DH];
__device__ float g_gates[(size_t)BSZ * GN];
__device__ float g_htnorm[(size_t)BSZ * DH];
__device__ float g_act[(size_t)BSZ * DPAD];
__device__ float g_Wall[(size_t)DIN * GN];
__device__ float g_Rall[(size_t)HD * GN];
__device__ float g_bias[GN];
__device__ float g_WupS[(size_t)DIN * NPAD];
__device__ float g_WupG[(size_t)DIN * NPAD];
__device__ float g_Wd[(size_t)DPAD * DIN];

// ---------------------------------------------------------------------------
// helpers
// ---------------------------------------------------------------------------
__device__ __forceinline__ float tf32r(float x) {
    unsigned u;
    asm("cvt.rna.tf32.f32 %0, %1;" : "=r"(u) : "f"(x));
    return __uint_as_float(u);
}
__device__ __forceinline__ float4 tf32r4(float4 v) {
    v.x = tf32r(v.x); v.y = tf32r(v.y); v.z = tf32r(v.z); v.w = tf32r(v.w);
    return v;
}
__device__ __forceinline__ void mma8(float* c, const unsigned* a, const unsigned* b) {
    asm volatile(
        "mma.sync.aligned.m16n8k8.row.col.f32.tf32.tf32.f32 "
        "{%0,%1,%2,%3}, {%4,%5,%6,%7}, {%8,%9}, {%0,%1,%2,%3};"
        : "+f"(c[0]), "+f"(c[1]), "+f"(c[2]), "+f"(c[3])
        : "r"(a[0]), "r"(a[1]), "r"(a[2]), "r"(a[3]), "r"(b[0]), "r"(b[1]));
}
__device__ __forceinline__ void cp16(void* dst, const void* src) {
    unsigned d = (unsigned)__cvta_generic_to_shared(dst);
    asm volatile("cp.async.cg.shared.global [%0], [%1], 16;\n" :: "r"(d), "l"(src));
}
#define CP_COMMIT asm volatile("cp.async.commit_group;\n")
#define CP_WAIT1  asm volatile("cp.async.wait_group 1;\n")

// ---------------------------------------------------------------------------
// Repack kernels (run every launch; all tf32-rounded)
// ---------------------------------------------------------------------------
__global__ __launch_bounds__(256) void repack_wall(
    const float* __restrict__ Wz, const float* __restrict__ Wi,
    const float* __restrict__ Wf, const float* __restrict__ Wo,
    const float* __restrict__ bz, const float* __restrict__ bi,
    const float* __restrict__ bf, const float* __restrict__ bo,
    const float* __restrict__ rbz, const float* __restrict__ rbi,
    const float* __restrict__ rbf, const float* __restrict__ rbo)
{
    int idx = blockIdx.x * 256 + threadIdx.x;           // DIN*GN = 4M
    if (idx >= DIN * GN) return;
    int k = idx >> 12, c = idx & 4095;
    int g = c >> 10, cl = c & 1023;
    const float* W = (g == 0) ? Wz : (g == 1) ? Wi : (g == 2) ? Wf : Wo;
    g_Wall[idx] = tf32r(W[(size_t)k * DH + cl]);
    if (k == 0) {
        const float* b  = (g == 0) ? bz  : (g == 1) ? bi  : (g == 2) ? bf  : bo;
        const float* rb = (g == 0) ? rbz : (g == 1) ? rbi : (g == 2) ? rbf : rbo;
        g_bias[c] = b[cl] + rb[cl];
    }
}

__global__ __launch_bounds__(256) void repack_rall(
    const float* __restrict__ Rz, const float* __restrict__ Ri,
    const float* __restrict__ Rf, const float* __restrict__ Ro)
{
    int idx = blockIdx.x * 256 + threadIdx.x;           // HD*GN = 1M
    if (idx >= HD * GN) return;
    int k2 = idx >> 12, c = idx & 4095;
    int g = c >> 10, head = (c >> 8) & 3, e = c & 255;
    const float* R = (g == 0) ? Rz : (g == 1) ? Ri : (g == 2) ? Rf : Ro;
    g_Rall[idx] = tf32r(R[head * 65536 + k2 * 256 + e]);
}

__global__ __launch_bounds__(256) void repack_wup(const float* __restrict__ Wup)
{
    int idx = blockIdx.x * 256 + threadIdx.x;
    if (idx >= DIN * NPAD) return;
    int k = idx / NPAD, c = idx % NPAD;
    float s = 0.f, g = 0.f;
    if (c < DP) {
        const float* row = Wup + (size_t)k * (2 * DP);
        s = tf32r(row[c]);
        g = tf32r(row[c + DP]);
    }
    g_WupS[idx] = s;
    g_WupG[idx] = g;
}

__global__ __launch_bounds__(256) void repack_wd(const float* __restrict__ Wd)
{
    int idx = blockIdx.x * 256 + threadIdx.x;
    if (idx >= DPAD * DIN) return;
    int k = idx >> 10, n = idx & 1023;
    g_Wd[idx] = (k < DP) ? tf32r(Wd[(size_t)k * DIN + n]) : 0.f;
}

__global__ __launch_bounds__(256) void round_h(const float* __restrict__ hp)
{
    int idx = blockIdx.x * 256 + threadIdx.x;           // PLANE/4
    if (idx >= PLANE / 4) return;
    float4 v = ((const float4*)hp)[idx];
    ((float4*)g_hr)[idx] = tf32r4(v);
}

// ---------------------------------------------------------------------------
// K1: LayerNorm over last dim (1024); output tf32-rounded (GEMM A operand).
// ---------------------------------------------------------------------------
__global__ __launch_bounds__(256) void ln_kernel(const float* __restrict__ x,
                                                 const float* __restrict__ w,
                                                 const float* __restrict__ b)
{
    int row = blockIdx.x;
    int tid = threadIdx.x;
    const float* xr = x + (size_t)row * DIN;
    float4 v = *(const float4*)(xr + tid * 4);
    float s  = v.x + v.y + v.z + v.w;
    float ss = v.x*v.x + v.y*v.y + v.z*v.z + v.w*v.w;

    __shared__ float red0[8], red1[8];
    unsigned lane = tid & 31, wid = tid >> 5;
    #pragma unroll
    for (int o = 16; o; o >>= 1) {
        s  += __shfl_down_sync(0xffffffffu, s,  o);
        ss += __shfl_down_sync(0xffffffffu, ss, o);
    }
    if (!lane) { red0[wid] = s; red1[wid] = ss; }
    __syncthreads();
    float S = 0.f, SS = 0.f;
    #pragma unroll
    for (int i = 0; i < 8; ++i) { S += red0[i]; SS += red1[i]; }
    float mean = S * (1.f / DIN);
    float var  = SS * (1.f / DIN) - mean * mean;
    float rstd = rsqrtf(var + 1e-5f);

    float4 wv = *(const float4*)(w + tid * 4);
    float4 bv = *(const float4*)(b + tid * 4);
    float4 o4;
    o4.x = (v.x - mean) * rstd * wv.x + bv.x;
    o4.y = (v.y - mean) * rstd * wv.y + bv.y;
    o4.z = (v.z - mean) * rstd * wv.z + bv.z;
    o4.w = (v.w - mean) * rstd * wv.w + bv.w;
    *(float4*)(g_xnorm + (size_t)row * DIN + tid * 4) = tf32r4(o4);
}

// ---------------------------------------------------------------------------
// K2: gates GEMM, cp.async 3-stage, tf32 mma. BM=128,BN=128,BK=16, K=1280.
// ---------------------------------------------------------------------------
__global__ __launch_bounds__(256) void gates_mma()
{
    extern __shared__ float sm[];

    const int row0 = blockIdx.y * 128;
    const int col0 = blockIdx.x * 128;
    const int head = (col0 >> 8) & 3;

    const int tid  = threadIdx.x;
    const int lane = tid & 31, wid = tid >> 5;
    const int wm = wid & 3, wn = wid >> 2;
    const int grp = lane >> 2, tig = lane & 3;

    const int am0 = tid >> 2;
    const int ak  = (tid & 3) * 4;
    const int bk0 = tid >> 5;
    const int bn  = (tid & 31) * 4;

    auto issue = [&](int kt) {
        float* A = sm + (kt % NSTAGE) * STG_G;
        float* B = A + 128 * SA;
        const float *Asrc, *Bsrc;
        if (kt < 64) {
            Asrc = g_xnorm + (size_t)row0 * DIN + kt * 16;
            Bsrc = g_Wall + (size_t)(kt * 16) * GN + col0;
        } else {
            int k2 = (kt - 64) * 16;
            Asrc = g_hr + (size_t)row0 * DH + head * HD + k2;
            Bsrc = g_Rall + (size_t)k2 * GN + col0;
        }
        cp16(&A[am0 * SA + ak],        Asrc + (size_t)am0 * DIN + ak);
        cp16(&A[(am0 + 64) * SA + ak], Asrc + (size_t)(am0 + 64) * DIN + ak);
        cp16(&B[bk0 * SB + bn],        Bsrc + (size_t)bk0 * GN + bn);
        cp16(&B[(bk0 + 8) * SB + bn],  Bsrc + (size_t)(bk0 + 8) * GN + bn);
    };

    float acc[2][8][4];
    #pragma unroll
    for (int mi = 0; mi < 2; ++mi)
        #pragma unroll
        for (int ni = 0; ni < 8; ++ni)
            #pragma unroll
            for (int q = 0; q < 4; ++q) acc[mi][ni][q] = 0.f;

    issue(0); CP_COMMIT;
    issue(1); CP_COMMIT;

    for (int kt = 0; kt < 80; ++kt) {
        CP_WAIT1;
        __syncthreads();
        if (kt + 2 < 80) issue(kt + 2);
        CP_COMMIT;

        const float* A = sm + (kt % NSTAGE) * STG_G;
        const float* B = A + 128 * SA;
        #pragma unroll
        for (int ks = 0; ks < 2; ++ks) {
            const int kk = ks * 8;
            unsigned af[2][4], bf4[8][2];
            #pragma unroll
            for (int mi = 0; mi < 2; ++mi) {
                int r = wm * 32 + mi * 16 + grp;
                af[mi][0] = __float_as_uint(A[r * SA + kk + tig]);
                af[mi][1] = __float_as_uint(A[(r + 8) * SA + kk + tig]);
                af[mi][2] = __float_as_uint(A[r * SA + kk + tig + 4]);
                af[mi][3] = __float_as_uint(A[(r + 8) * SA + kk + tig + 4]);
            }
            #pragma unroll
            for (int ni = 0; ni < 8; ++ni) {
                int c = wn * 64 + ni * 8 + grp;
                bf4[ni][0] = __float_as_uint(B[(kk + tig) * SB + c]);
                bf4[ni][1] = __float_as_uint(B[(kk + tig + 4) * SB + c]);
            }
            #pragma unroll
            for (int mi = 0; mi < 2; ++mi)
                #pragma unroll
                for (int ni = 0; ni < 8; ++ni)
                    mma8(acc[mi][ni], af[mi], bf4[ni]);
        }
    }

    #pragma unroll
    for (int mi = 0; mi < 2; ++mi) {
        int r = row0 + wm * 32 + mi * 16 + grp;
        #pragma unroll
        for (int ni = 0; ni < 8; ++ni) {
            int c = col0 + wn * 64 + ni * 8 + tig * 2;
            float b0 = g_bias[c], b1 = g_bias[c + 1];
            float2 v0 = {acc[mi][ni][0] + b0, acc[mi][ni][1] + b1};
            float2 v1 = {acc[mi][ni][2] + b0, acc[mi][ni][3] + b1};
            *(float2*)&g_gates[(size_t)r * GN + c]       = v0;
            *(float2*)&g_gates[(size_t)(r + 8) * GN + c] = v1;
        }
    }
}

// ---------------------------------------------------------------------------
// K3: sLSTM cell + per-head GroupNorm; g_htnorm tf32-rounded.
// ---------------------------------------------------------------------------
__global__ __launch_bounds__(256) void cell_kernel(
    const float* __restrict__ cp, const float* __restrict__ np,
    const float* __restrict__ mp,
    const float* __restrict__ gnw, const float* __restrict__ gnb,
    float* __restrict__ ht_o, float* __restrict__ ct_o,
    float* __restrict__ nt_o, float* __restrict__ mt_o)
{
    int bh = blockIdx.x;
    int b = bh >> 2, h = bh & 3;
    int d = threadIdx.x;
    size_t idx   = (size_t)b * DH + h * 256 + d;
    size_t gbase = (size_t)b * GN + h * 256 + d;

    float z  = g_gates[gbase];
    float i_ = g_gates[gbase + 1024];
    float f_ = g_gates[gbase + 2048];
    float o_ = g_gates[gbase + 3072];
    float mpv = mp[idx], cpv = cp[idx], npv = np[idx];

    float zt = tanhf(z);
    float ot = 1.f / (1.f + expf(-o_));
    float fm = f_ + mpv;
    float mt = fmaxf(fm, i_);
    float it = expf(i_ - mt);
    float ft = expf(fm - mt);
    float ct = ft * cpv + it * zt;
    float nt = ft * npv + it;
    float ht = ot * (ct / (nt + 1e-13f));

    ht_o[idx] = ht; ct_o[idx] = ct; nt_o[idx] = nt; mt_o[idx] = mt;

    float s = ht, ss = ht * ht;
    __shared__ float red0[8], red1[8];
    unsigned lane = d & 31, wid = d >> 5;
    #pragma unroll
    for (int o = 16; o; o >>= 1) {
        s  += __shfl_down_sync(0xffffffffu, s,  o);
        ss += __shfl_down_sync(0xffffffffu, ss, o);
    }
    if (!lane) { red0[wid] = s; red1[wid] = ss; }
    __syncthreads();
    float S = 0.f, SS = 0.f;
    #pragma unroll
    for (int i = 0; i < 8; ++i) { S += red0[i]; SS += red1[i]; }
    float mean = S * (1.f / 256.f);
    float var  = SS * (1.f / 256.f) - mean * mean;
    float rstd = rsqrtf(var + 1e-5f);
    int c = h * 256 + d;
    g_htnorm[idx] = tf32r((ht - mean) * rstd * gnw[c] + gnb[c]);
}

// ---------------------------------------------------------------------------
// K4: up-projection + GeGLU, cp.async 3-stage, dual-B. BM=128,BN=64,BK=16.
// ---------------------------------------------------------------------------
__global__ __launch_bounds__(256) void upact_mma(const float* __restrict__ bup)
{
    extern __shared__ float sm[];

    const int row0 = blockIdx.y * 128;
    const int col0 = blockIdx.x * 64;

    const int tid  = threadIdx.x;
    const int lane = tid & 31, wid = tid >> 5;
    const int wm = wid & 3, wn = wid >> 2;
    const int grp = lane >> 2, tig = lane & 3;

    const int am0 = tid >> 2;
    const int ak  = (tid & 3) * 4;
    const int bk  = tid >> 4;
    const int bnU = (tid & 15) * 4;

    auto issue = [&](int kt) {
        float* A  = sm + (kt % NSTAGE) * STG_U;
        float* BS = A + 128 * SA;
        float* BG = BS + 16 * SBU;
        const float* Asrc = g_htnorm + (size_t)row0 * DH + kt * 16;
        cp16(&A[am0 * SA + ak],        Asrc + (size_t)am0 * DH + ak);
        cp16(&A[(am0 + 64) * SA + ak], Asrc + (size_t)(am0 + 64) * DH + ak);
        size_t boff = (size_t)(kt * 16 + bk) * NPAD + col0 + bnU;
        cp16(&BS[bk * SBU + bnU], g_WupS + boff);
        cp16(&BG[bk * SBU + bnU], g_WupG + boff);
    };

    float accS[2][4][4], accG[2][4][4];
    #pragma unroll
    for (int mi = 0; mi < 2; ++mi)
        #pragma unroll
        for (int ni = 0; ni < 4; ++ni)
            #pragma unroll
            for (int q = 0; q < 4; ++q) { accS[mi][ni][q] = 0.f; accG[mi][ni][q] = 0.f; }

    issue(0); CP_COMMIT;
    issue(1); CP_COMMIT;

    for (int kt = 0; kt < 64; ++kt) {
        CP_WAIT1;
        __syncthreads();
        if (kt + 2 < 64) issue(kt + 2);
        CP_COMMIT;

        const float* A  = sm + (kt % NSTAGE) * STG_U;
        const float* BS = A + 128 * SA;
        const float* BG = BS + 16 * SBU;
        #pragma unroll
        for (int ks = 0; ks < 2; ++ks) {
            const int kk = ks * 8;
            unsigned af[2][4], bs[4][2], bg[4][2];
            #pragma unroll
            for (int mi = 0; mi < 2; ++mi) {
                int r = wm * 32 + mi * 16 + grp;
                af[mi][0] = __float_as_uint(A[r * SA + kk + tig]);
                af[mi][1] = __float_as_uint(A[(r + 8) * SA + kk + tig]);
                af[mi][2] = __float_as_uint(A[r * SA + kk + tig + 4]);
                af[mi][3] = __float_as_uint(A[(r + 8) * SA + kk + tig + 4]);
            }
            #pragma unroll
            for (int ni = 0; ni < 4; ++ni) {
                int c = wn * 32 + ni * 8 + grp;
                bs[ni][0] = __float_as_uint(BS[(kk + tig) * SBU + c]);
                bs[ni][1] = __float_as_uint(BS[(kk + tig + 4) * SBU + c]);
                bg[ni][0] = __float_as_uint(BG[(kk + tig) * SBU + c]);
                bg[ni][1] = __float_as_uint(BG[(kk + tig + 4) * SBU + c]);
            }
            #pragma unroll
            for (int mi = 0; mi < 2; ++mi)
                #pragma unroll
                for (int ni = 0; ni < 4; ++ni) {
                    mma8(accS[mi][ni], af[mi], bs[ni]);
                    mma8(accG[mi][ni], af[mi], bg[ni]);
                }
        }
    }

    #pragma unroll
    for (int mi = 0; mi < 2; ++mi) {
        int r = row0 + wm * 32 + mi * 16 + grp;
        #pragma unroll
        for (int ni = 0; ni < 4; ++ni) {
            int c = col0 + wn * 32 + ni * 8 + tig * 2;
            #pragma unroll
            for (int half = 0; half < 2; ++half) {
                int rr = r + half * 8;
                #pragma unroll
                for (int j = 0; j < 2; ++j) {
                    int cc = c + j;
                    if (cc < DPAD) {
                        float v = 0.f;
                        if (cc < DP) {
                            float sv = accS[mi][ni][half * 2 + j] + bup[cc];
                            float gv = accG[mi][ni][half * 2 + j] + bup[cc + DP];
                            float ge = 0.5f * gv * (1.f + erff(gv * 0.70710678118654752f));
                            v = tf32r(sv * ge);
                        }
                        g_act[(size_t)rr * DPAD + cc] = v;
                    }
                }
            }
        }
    }
}

// ---------------------------------------------------------------------------
// K5: down GEMM + residual, cp.async 3-stage. BM=128,BN=128,BK=16,K=1376.
// ---------------------------------------------------------------------------
__global__ __launch_bounds__(256) void down_mma(const float* __restrict__ x,
                                                const float* __restrict__ bd,
                                                float* __restrict__ y)
{
    extern __shared__ float sm[];

    const int row0 = blockIdx.y * 128;
    const int col0 = blockIdx.x * 128;

    const int tid  = threadIdx.x;
    const int lane = tid & 31, wid = tid >> 5;
    const int wm = wid & 3, wn = wid >> 2;
    const int grp = lane >> 2, tig = lane & 3;

    const int am0 = tid >> 2;
    const int ak  = (tid & 3) * 4;
    const int bk0 = tid >> 5;
    const int bn  = (tid & 31) * 4;

    auto issue = [&](int kt) {
        float* A = sm + (kt % NSTAGE) * STG_G;
        float* B = A + 128 * SA;
        const float* Asrc = g_act + (size_t)row0 * DPAD + kt * 16;
        const float* Bsrc = g_Wd + (size_t)(kt * 16) * DIN + col0;
        cp16(&A[am0 * SA + ak],        Asrc + (size_t)am0 * DPAD + ak);
        cp16(&A[(am0 + 64) * SA + ak], Asrc + (size_t)(am0 + 64) * DPAD + ak);
        cp16(&B[bk0 * SB + bn],        Bsrc + (size_t)bk0 * DIN + bn);
        cp16(&B[(bk0 + 8) * SB + bn],  Bsrc + (size_t)(bk0 + 8) * DIN + bn);
    };

    float acc[2][8][4];
    #pragma unroll
    for (int mi = 0; mi < 2; ++mi)
        #pragma unroll
        for (int ni = 0; ni < 8; ++ni)
            #pragma unroll
            for (int q = 0; q < 4; ++q) acc[mi][ni][q] = 0.f;

    issue(0); CP_COMMIT;
    issue(1); CP_COMMIT;

    const int NT = DPAD / 16;  // 86
    for (int kt = 0; kt < NT; ++kt) {
        CP_WAIT1;
        __syncthreads();
        if (kt + 2 < NT) issue(kt + 2);
        CP_COMMIT;

        const float* A = sm + (kt % NSTAGE) * STG_G;
        const float* B = A + 128 * SA;
        #pragma unroll
        for (int ks = 0; ks < 2; ++ks) {
            const int kk = ks * 8;
            unsigned af[2][4], bf4[8][2];
            #pragma unroll
            for (int mi = 0; mi < 2; ++mi) {
                int r = wm * 32 + mi * 16 + grp;
                af[mi][0] = __float_as_uint(A[r * SA + kk + tig]);
                af[mi][1] = __float_as_uint(A[(r + 8) * SA + kk + tig]);
                af[mi][2] = __float_as_uint(A[r * SA + kk + tig + 4]);
                af[mi][3] = __float_as_uint(A[(r + 8) * SA + kk + tig + 4]);
            }
            #pragma unroll
            for (int ni = 0; ni < 8; ++ni) {
                int c = wn * 64 + ni * 8 + grp;
                bf4[ni][0] = __float_as_uint(B[(kk + tig) * SB + c]);
                bf4[ni][1] = __float_as_uint(B[(kk + tig + 4) * SB + c]);
            }
            #pragma unroll
            for (int mi = 0; mi < 2; ++mi)
                #pragma unroll
                for (int ni = 0; ni < 8; ++ni)
                    mma8(acc[mi][ni], af[mi], bf4[ni]);
        }
    }

    #pragma unroll
    for (int mi = 0; mi < 2; ++mi) {
        int r = row0 + wm * 32 + mi * 16 + grp;
        #pragma unroll
        for (int ni = 0; ni < 8; ++ni) {
            int c = col0 + wn * 64 + ni * 8 + tig * 2;
            float b0 = bd[c], b1 = bd[c + 1];
            float2 x0 = *(const float2*)&x[(size_t)r * DIN + c];
            float2 x1 = *(const float2*)&x[(size_t)(r + 8) * DIN + c];
            float2 v0 = {acc[mi][ni][0] + b0 + x0.x, acc[mi][ni][1] + b1 + x0.y};
            float2 v1 = {acc[mi][ni][2] + b0 + x1.x, acc[mi][ni][3] + b1 + x1.y};
            *(float2*)&y[(size_t)r * DIN + c]       = v0;
            *(float2*)&y[(size_t)(r + 8) * DIN + c] = v1;
        }
    }
}

// ---------------------------------------------------------------------------
extern "C" void kernel_launch(void* const* d_in, const int* in_sizes, int n_in,
                              void* d_out, int out_size)
{
    const float* x      = (const float*)d_in[0];
    const float* h_prev = (const float*)d_in[1];
    const float* c_prev = (const float*)d_in[2];
    const float* n_prev = (const float*)d_in[3];
    const float* m_prev = (const float*)d_in[4];
    const float* ln_w   = (const float*)d_in[5];
    const float* ln_b   = (const float*)d_in[6];
    const float* Wz = (const float*)d_in[7];
    const float* bz = (const float*)d_in[8];
    const float* Wi = (const float*)d_in[9];
    const float* bi = (const float*)d_in[10];
    const float* Wf = (const float*)d_in[11];
    const float* bf = (const float*)d_in[12];
    const float* Wo = (const float*)d_in[13];
    const float* bo = (const float*)d_in[14];
    const float* Rz  = (const float*)d_in[15];
    const float* rbz = (const float*)d_in[16];
    const float* Ri  = (const float*)d_in[17];
    const float* rbi = (const float*)d_in[18];
    const float* Rf  = (const float*)d_in[19];
    const float* rbf = (const float*)d_in[20];
    const float* Ro  = (const float*)d_in[21];
    const float* rbo = (const float*)d_in[22];
    const float* gn_w = (const float*)d_in[23];
    const float* gn_b = (const float*)d_in[24];
    const float* Wup  = (const float*)d_in[25];
    const float* bup  = (const float*)d_in[26];
    const float* Wdown = (const float*)d_in[27];
    const float* bdown = (const float*)d_in[28];

    float* out  = (float*)d_out;
    float* y_o  = out;
    float* ht_o = out + (size_t)PLANE;
    float* ct_o = out + (size_t)2 * PLANE;
    float* nt_o = out + (size_t)3 * PLANE;
    float* mt_o = out + (size_t)4 * PLANE;

    const int smG = NSTAGE * STG_G * 4;   // 56832
    const int smU = NSTAGE * STG_U * 4;   // 58368
    cudaFuncSetAttribute(gates_mma, cudaFuncAttributeMaxDynamicSharedMemorySize, smG);
    cudaFuncSetAttribute(upact_mma, cudaFuncAttributeMaxDynamicSharedMemorySize, smU);
    cudaFuncSetAttribute(down_mma,  cudaFuncAttributeMaxDynamicSharedMemorySize, smG);

    repack_wall<<<(DIN * GN + 255) / 256, 256>>>(Wz, Wi, Wf, Wo, bz, bi, bf, bo,
                                                 rbz, rbi, rbf, rbo);
    repack_rall<<<(HD * GN + 255) / 256, 256>>>(Rz, Ri, Rf, Ro);
    repack_wup<<<(DIN * NPAD + 255) / 256, 256>>>(Wup);
    repack_wd<<<(DPAD * DIN + 255) / 256, 256>>>(Wdown);
    round_h<<<(PLANE / 4 + 255) / 256, 256>>>(h_prev);

    ln_kernel<<<BSZ, 256>>>(x, ln_w, ln_b);

    gates_mma<<<dim3(GN / 128, BSZ / 128), 256, smG>>>();

    cell_kernel<<<BSZ * NH, 256>>>(c_prev, n_prev, m_prev, gn_w, gn_b,
                                   ht_o, ct_o, nt_o, mt_o);

    upact_mma<<<dim3(NPAD / 64, BSZ / 128), 256, smU>>>(bup);

    down_mma<<<dim3(DIN / 128, BSZ / 128), 256, smG>>>(x, bdown, y_o);
}

// round 4
// speedup vs baseline: 3.0564x; 1.0008x over previous
#include <cuda_runtime.h>
#include <math.h>

// Problem constants
#define BSZ   8192
#define DIN   1024
#define DH    1024
#define NH    4
#define HD    256
#define DP    1365
#define DPAD  1376
#define NPAD  1408
#define GN    4096
#define PLANE (BSZ*DH)

#define SA  20
#define SB  136
#define SBU 72

// pipeline stage sizes (floats)
#define STG_G (128*SA + 16*SB)        // 4736
#define STG_U (128*SA + 2*16*SBU)     // 4864
#define NSTAGE 3

// Scratch (static device globals — allocation-free rule)
__device__ float g_xnorm[(size_t)BSZ * DIN];
__device__ float g_hr[(size_t)BSZ * DH];
__device__ float g_gates[(size_t)BSZ * GN];
__device__ float g_htnorm[(size_t)BSZ * DH];
__device__ float g_act[(size_t)BSZ * DPAD];
__device__ float g_Wall[(size_t)DIN * GN];
__device__ float g_Rall[(size_t)HD * GN];
__device__ float g_bias[GN];
__device__ float g_WupS[(size_t)DIN * NPAD];
__device__ float g_WupG[(size_t)DIN * NPAD];
__device__ float g_Wd[(size_t)DPAD * DIN];

// ---------------------------------------------------------------------------
// helpers
// ---------------------------------------------------------------------------
__device__ __forceinline__ float tf32r(float x) {
    unsigned u;
    asm("cvt.rna.tf32.f32 %0, %1;" : "=r"(u) : "f"(x));
    return __uint_as_float(u);
}
__device__ __forceinline__ float4 tf32r4(float4 v) {
    v.x = tf32r(v.x); v.y = tf32r(v.y); v.z = tf32r(v.z); v.w = tf32r(v.w);
    return v;
}
__device__ __forceinline__ void mma8(float* c, const unsigned* a, const unsigned* b) {
    asm volatile(
        "mma.sync.aligned.m16n8k8.row.col.f32.tf32.tf32.f32 "
        "{%0,%1,%2,%3}, {%4,%5,%6,%7}, {%8,%9}, {%0,%1,%2,%3};"
        : "+f"(c[0]), "+f"(c[1]), "+f"(c[2]), "+f"(c[3])
        : "r"(a[0]), "r"(a[1]), "r"(a[2]), "r"(a[3]), "r"(b[0]), "r"(b[1]));
}
__device__ __forceinline__ void cp16(void* dst, const void* src) {
    unsigned d = (unsigned)__cvta_generic_to_shared(dst);
    asm volatile("cp.async.cg.shared.global [%0], [%1], 16;\n" :: "r"(d), "l"(src));
}
#define CP_COMMIT asm volatile("cp.async.commit_group;\n")
#define CP_WAIT1  asm volatile("cp.async.wait_group 1;\n")

// ---------------------------------------------------------------------------
// Repack kernels (run every launch; all tf32-rounded)
// ---------------------------------------------------------------------------
__global__ __launch_bounds__(256) void repack_wall(
    const float* __restrict__ Wz, const float* __restrict__ Wi,
    const float* __restrict__ Wf, const float* __restrict__ Wo,
    const float* __restrict__ bz, const float* __restrict__ bi,
    const float* __restrict__ bf, const float* __restrict__ bo,
    const float* __restrict__ rbz, const float* __restrict__ rbi,
    const float* __restrict__ rbf, const float* __restrict__ rbo)
{
    int idx = blockIdx.x * 256 + threadIdx.x;           // DIN*GN = 4M
    if (idx >= DIN * GN) return;
    int k = idx >> 12, c = idx & 4095;
    int g = c >> 10, cl = c & 1023;
    const float* W = (g == 0) ? Wz : (g == 1) ? Wi : (g == 2) ? Wf : Wo;
    g_Wall[idx] = tf32r(W[(size_t)k * DH + cl]);
    if (k == 0) {
        const float* b  = (g == 0) ? bz  : (g == 1) ? bi  : (g == 2) ? bf  : bo;
        const float* rb = (g == 0) ? rbz : (g == 1) ? rbi : (g == 2) ? rbf : rbo;
        g_bias[c] = b[cl] + rb[cl];
    }
}

__global__ __launch_bounds__(256) void repack_rall(
    const float* __restrict__ Rz, const float* __restrict__ Ri,
    const float* __restrict__ Rf, const float* __restrict__ Ro)
{
    int idx = blockIdx.x * 256 + threadIdx.x;           // HD*GN = 1M
    if (idx >= HD * GN) return;
    int k2 = idx >> 12, c = idx & 4095;
    int g = c >> 10, head = (c >> 8) & 3, e = c & 255;
    const float* R = (g == 0) ? Rz : (g == 1) ? Ri : (g == 2) ? Rf : Ro;
    g_Rall[idx] = tf32r(R[head * 65536 + k2 * 256 + e]);
}

__global__ __launch_bounds__(256) void repack_wup(const float* __restrict__ Wup)
{
    int idx = blockIdx.x * 256 + threadIdx.x;
    if (idx >= DIN * NPAD) return;
    int k = idx / NPAD, c = idx % NPAD;
    float s = 0.f, g = 0.f;
    if (c < DP) {
        const float* row = Wup + (size_t)k * (2 * DP);
        s = tf32r(row[c]);
        g = tf32r(row[c + DP]);
    }
    g_WupS[idx] = s;
    g_WupG[idx] = g;
}

__global__ __launch_bounds__(256) void repack_wd(const float* __restrict__ Wd)
{
    int idx = blockIdx.x * 256 + threadIdx.x;
    if (idx >= DPAD * DIN) return;
    int k = idx >> 10, n = idx & 1023;
    g_Wd[idx] = (k < DP) ? tf32r(Wd[(size_t)k * DIN + n]) : 0.f;
}

__global__ __launch_bounds__(256) void round_h(const float* __restrict__ hp)
{
    int idx = blockIdx.x * 256 + threadIdx.x;           // PLANE/4
    if (idx >= PLANE / 4) return;
    float4 v = ((const float4*)hp)[idx];
    ((float4*)g_hr)[idx] = tf32r4(v);
}

// ---------------------------------------------------------------------------
// K1: LayerNorm over last dim (1024); output tf32-rounded (GEMM A operand).
// ---------------------------------------------------------------------------
__global__ __launch_bounds__(256) void ln_kernel(const float* __restrict__ x,
                                                 const float* __restrict__ w,
                                                 const float* __restrict__ b)
{
    int row = blockIdx.x;
    int tid = threadIdx.x;
    const float* xr = x + (size_t)row * DIN;
    float4 v = *(const float4*)(xr + tid * 4);
    float s  = v.x + v.y + v.z + v.w;
    float ss = v.x*v.x + v.y*v.y + v.z*v.z + v.w*v.w;

    __shared__ float red0[8], red1[8];
    unsigned lane = tid & 31, wid = tid >> 5;
    #pragma unroll
    for (int o = 16; o; o >>= 1) {
        s  += __shfl_down_sync(0xffffffffu, s,  o);
        ss += __shfl_down_sync(0xffffffffu, ss, o);
    }
    if (!lane) { red0[wid] = s; red1[wid] = ss; }
    __syncthreads();
    float S = 0.f, SS = 0.f;
    #pragma unroll
    for (int i = 0; i < 8; ++i) { S += red0[i]; SS += red1[i]; }
    float mean = S * (1.f / DIN);
    float var  = SS * (1.f / DIN) - mean * mean;
    float rstd = rsqrtf(var + 1e-5f);

    float4 wv = *(const float4*)(w + tid * 4);
    float4 bv = *(const float4*)(b + tid * 4);
    float4 o4;
    o4.x = (v.x - mean) * rstd * wv.x + bv.x;
    o4.y = (v.y - mean) * rstd * wv.y + bv.y;
    o4.z = (v.z - mean) * rstd * wv.z + bv.z;
    o4.w = (v.w - mean) * rstd * wv.w + bv.w;
    *(float4*)(g_xnorm + (size_t)row * DIN + tid * 4) = tf32r4(o4);
}

// ---------------------------------------------------------------------------
// K2: gates GEMM, cp.async 3-stage, tf32 mma. BM=128,BN=128,BK=16, K=1280.
// ---------------------------------------------------------------------------
__global__ __launch_bounds__(256) void gates_mma()
{
    extern __shared__ float sm[];

    const int row0 = blockIdx.y * 128;
    const int col0 = blockIdx.x * 128;
    const int head = (col0 >> 8) & 3;

    const int tid  = threadIdx.x;
    const int lane = tid & 31, wid = tid >> 5;
    const int wm = wid & 3, wn = wid >> 2;
    const int grp = lane >> 2, tig = lane & 3;

    const int am0 = tid >> 2;
    const int ak  = (tid & 3) * 4;
    const int bk0 = tid >> 5;
    const int bn  = (tid & 31) * 4;

    auto issue = [&](int kt) {
        float* A = sm + (kt % NSTAGE) * STG_G;
        float* B = A + 128 * SA;
        const float *Asrc, *Bsrc;
        if (kt < 64) {
            Asrc = g_xnorm + (size_t)row0 * DIN + kt * 16;
            Bsrc = g_Wall + (size_t)(kt * 16) * GN + col0;
        } else {
            int k2 = (kt - 64) * 16;
            Asrc = g_hr + (size_t)row0 * DH + head * HD + k2;
            Bsrc = g_Rall + (size_t)k2 * GN + col0;
        }
        cp16(&A[am0 * SA + ak],        Asrc + (size_t)am0 * DIN + ak);
        cp16(&A[(am0 + 64) * SA + ak], Asrc + (size_t)(am0 + 64) * DIN + ak);
        cp16(&B[bk0 * SB + bn],        Bsrc + (size_t)bk0 * GN + bn);
        cp16(&B[(bk0 + 8) * SB + bn],  Bsrc + (size_t)(bk0 + 8) * GN + bn);
    };

    float acc[2][8][4];
    #pragma unroll
    for (int mi = 0; mi < 2; ++mi)
        #pragma unroll
        for (int ni = 0; ni < 8; ++ni)
            #pragma unroll
            for (int q = 0; q < 4; ++q) acc[mi][ni][q] = 0.f;

    issue(0); CP_COMMIT;
    issue(1); CP_COMMIT;

    for (int kt = 0; kt < 80; ++kt) {
        CP_WAIT1;
        __syncthreads();
        if (kt + 2 < 80) issue(kt + 2);
        CP_COMMIT;

        const float* A = sm + (kt % NSTAGE) * STG_G;
        const float* B = A + 128 * SA;
        #pragma unroll
        for (int ks = 0; ks < 2; ++ks) {
            const int kk = ks * 8;
            unsigned af[2][4], bf4[8][2];
            #pragma unroll
            for (int mi = 0; mi < 2; ++mi) {
                int r = wm * 32 + mi * 16 + grp;
                af[mi][0] = __float_as_uint(A[r * SA + kk + tig]);
                af[mi][1] = __float_as_uint(A[(r + 8) * SA + kk + tig]);
                af[mi][2] = __float_as_uint(A[r * SA + kk + tig + 4]);
                af[mi][3] = __float_as_uint(A[(r + 8) * SA + kk + tig + 4]);
            }
            #pragma unroll
            for (int ni = 0; ni < 8; ++ni) {
                int c = wn * 64 + ni * 8 + grp;
                bf4[ni][0] = __float_as_uint(B[(kk + tig) * SB + c]);
                bf4[ni][1] = __float_as_uint(B[(kk + tig + 4) * SB + c]);
            }
            #pragma unroll
            for (int mi = 0; mi < 2; ++mi)
                #pragma unroll
                for (int ni = 0; ni < 8; ++ni)
                    mma8(acc[mi][ni], af[mi], bf4[ni]);
        }
    }

    #pragma unroll
    for (int mi = 0; mi < 2; ++mi) {
        int r = row0 + wm * 32 + mi * 16 + grp;
        #pragma unroll
        for (int ni = 0; ni < 8; ++ni) {
            int c = col0 + wn * 64 + ni * 8 + tig * 2;
            float b0 = g_bias[c], b1 = g_bias[c + 1];
            float2 v0 = {acc[mi][ni][0] + b0, acc[mi][ni][1] + b1};
            float2 v1 = {acc[mi][ni][2] + b0, acc[mi][ni][3] + b1};
            *(float2*)&g_gates[(size_t)r * GN + c]       = v0;
            *(float2*)&g_gates[(size_t)(r + 8) * GN + c] = v1;
        }
    }
}

// ---------------------------------------------------------------------------
// K3: sLSTM cell + per-head GroupNorm; g_htnorm tf32-rounded.
// ---------------------------------------------------------------------------
__global__ __launch_bounds__(256) void cell_kernel(
    const float* __restrict__ cp, const float* __restrict__ np,
    const float* __restrict__ mp,
    const float* __restrict__ gnw, const float* __restrict__ gnb,
    float* __restrict__ ht_o, float* __restrict__ ct_o,
    float* __restrict__ nt_o, float* __restrict__ mt_o)
{
    int bh = blockIdx.x;
    int b = bh >> 2, h = bh & 3;
    int d = threadIdx.x;
    size_t idx   = (size_t)b * DH + h * 256 + d;
    size_t gbase = (size_t)b * GN + h * 256 + d;

    float z  = g_gates[gbase];
    float i_ = g_gates[gbase + 1024];
    float f_ = g_gates[gbase + 2048];
    float o_ = g_gates[gbase + 3072];
    float mpv = mp[idx], cpv = cp[idx], npv = np[idx];

    float zt = tanhf(z);
    float ot = 1.f / (1.f + expf(-o_));
    float fm = f_ + mpv;
    float mt = fmaxf(fm, i_);
    float it = expf(i_ - mt);
    float ft = expf(fm - mt);
    float ct = ft * cpv + it * zt;
    float nt = ft * npv + it;
    float ht = ot * (ct / (nt + 1e-13f));

    ht_o[idx] = ht; ct_o[idx] = ct; nt_o[idx] = nt; mt_o[idx] = mt;

    float s = ht, ss = ht * ht;
    __shared__ float red0[8], red1[8];
    unsigned lane = d & 31, wid = d >> 5;
    #pragma unroll
    for (int o = 16; o; o >>= 1) {
        s  += __shfl_down_sync(0xffffffffu, s,  o);
        ss += __shfl_down_sync(0xffffffffu, ss, o);
    }
    if (!lane) { red0[wid] = s; red1[wid] = ss; }
    __syncthreads();
    float S = 0.f, SS = 0.f;
    #pragma unroll
    for (int i = 0; i < 8; ++i) { S += red0[i]; SS += red1[i]; }
    float mean = S * (1.f / 256.f);
    float var  = SS * (1.f / 256.f) - mean * mean;
    float rstd = rsqrtf(var + 1e-5f);
    int c = h * 256 + d;
    g_htnorm[idx] = tf32r((ht - mean) * rstd * gnw[c] + gnb[c]);
}

// ---------------------------------------------------------------------------
// K4: up-projection + GeGLU, cp.async 3-stage, dual-B. BM=128,BN=64,BK=16.
// ---------------------------------------------------------------------------
__global__ __launch_bounds__(256) void upact_mma(const float* __restrict__ bup)
{
    extern __shared__ float sm[];

    const int row0 = blockIdx.y * 128;
    const int col0 = blockIdx.x * 64;

    const int tid  = threadIdx.x;
    const int lane = tid & 31, wid = tid >> 5;
    const int wm = wid & 3, wn = wid >> 2;
    const int grp = lane >> 2, tig = lane & 3;

    const int am0 = tid >> 2;
    const int ak  = (tid & 3) * 4;
    const int bk  = tid >> 4;
    const int bnU = (tid & 15) * 4;

    auto issue = [&](int kt) {
        float* A  = sm + (kt % NSTAGE) * STG_U;
        float* BS = A + 128 * SA;
        float* BG = BS + 16 * SBU;
        const float* Asrc = g_htnorm + (size_t)row0 * DH + kt * 16;
        cp16(&A[am0 * SA + ak],        Asrc + (size_t)am0 * DH + ak);
        cp16(&A[(am0 + 64) * SA + ak], Asrc + (size_t)(am0 + 64) * DH + ak);
        size_t boff = (size_t)(kt * 16 + bk) * NPAD + col0 + bnU;
        cp16(&BS[bk * SBU + bnU], g_WupS + boff);
        cp16(&BG[bk * SBU + bnU], g_WupG + boff);
    };

    float accS[2][4][4], accG[2][4][4];
    #pragma unroll
    for (int mi = 0; mi < 2; ++mi)
        #pragma unroll
        for (int ni = 0; ni < 4; ++ni)
            #pragma unroll
            for (int q = 0; q < 4; ++q) { accS[mi][ni][q] = 0.f; accG[mi][ni][q] = 0.f; }

    issue(0); CP_COMMIT;
    issue(1); CP_COMMIT;

    for (int kt = 0; kt < 64; ++kt) {
        CP_WAIT1;
        __syncthreads();
        if (kt + 2 < 64) issue(kt + 2);
        CP_COMMIT;

        const float* A  = sm + (kt % NSTAGE) * STG_U;
        const float* BS = A + 128 * SA;
        const float* BG = BS + 16 * SBU;
        #pragma unroll
        for (int ks = 0; ks < 2; ++ks) {
            const int kk = ks * 8;
            unsigned af[2][4], bs[4][2], bg[4][2];
            #pragma unroll
            for (int mi = 0; mi < 2; ++mi) {
                int r = wm * 32 + mi * 16 + grp;
                af[mi][0] = __float_as_uint(A[r * SA + kk + tig]);
                af[mi][1] = __float_as_uint(A[(r + 8) * SA + kk + tig]);
                af[mi][2] = __float_as_uint(A[r * SA + kk + tig + 4]);
                af[mi][3] = __float_as_uint(A[(r + 8) * SA + kk + tig + 4]);
            }
            #pragma unroll
            for (int ni = 0; ni < 4; ++ni) {
                int c = wn * 32 + ni * 8 + grp;
                bs[ni][0] = __float_as_uint(BS[(kk + tig) * SBU + c]);
                bs[ni][1] = __float_as_uint(BS[(kk + tig + 4) * SBU + c]);
                bg[ni][0] = __float_as_uint(BG[(kk + tig) * SBU + c]);
                bg[ni][1] = __float_as_uint(BG[(kk + tig + 4) * SBU + c]);
            }
            #pragma unroll
            for (int mi = 0; mi < 2; ++mi)
                #pragma unroll
                for (int ni = 0; ni < 4; ++ni) {
                    mma8(accS[mi][ni], af[mi], bs[ni]);
                    mma8(accG[mi][ni], af[mi], bg[ni]);
                }
        }
    }

    #pragma unroll
    for (int mi = 0; mi < 2; ++mi) {
        int r = row0 + wm * 32 + mi * 16 + grp;
        #pragma unroll
        for (int ni = 0; ni < 4; ++ni) {
            int c = col0 + wn * 32 + ni * 8 + tig * 2;
            #pragma unroll
            for (int half = 0; half < 2; ++half) {
                int rr = r + half * 8;
                #pragma unroll
                for (int j = 0; j < 2; ++j) {
                    int cc = c + j;
                    if (cc < DPAD) {
                        float v = 0.f;
                        if (cc < DP) {
                            float sv = accS[mi][ni][half * 2 + j] + bup[cc];
                            float gv = accG[mi][ni][half * 2 + j] + bup[cc + DP];
                            float ge = 0.5f * gv * (1.f + erff(gv * 0.70710678118654752f));
                            v = tf32r(sv * ge);
                        }
                        g_act[(size_t)rr * DPAD + cc] = v;
                    }
                }
            }
        }
    }
}

// ---------------------------------------------------------------------------
// K5: down GEMM + residual, cp.async 3-stage. BM=128,BN=128,BK=16,K=1376.
// ---------------------------------------------------------------------------
__global__ __launch_bounds__(256) void down_mma(const float* __restrict__ x,
                                                const float* __restrict__ bd,
                                                float* __restrict__ y)
{
    extern __shared__ float sm[];

    const int row0 = blockIdx.y * 128;
    const int col0 = blockIdx.x * 128;

    const int tid  = threadIdx.x;
    const int lane = tid & 31, wid = tid >> 5;
    const int wm = wid & 3, wn = wid >> 2;
    const int grp = lane >> 2, tig = lane & 3;

    const int am0 = tid >> 2;
    const int ak  = (tid & 3) * 4;
    const int bk0 = tid >> 5;
    const int bn  = (tid & 31) * 4;

    auto issue = [&](int kt) {
        float* A = sm + (kt % NSTAGE) * STG_G;
        float* B = A + 128 * SA;
        const float* Asrc = g_act + (size_t)row0 * DPAD + kt * 16;
        const float* Bsrc = g_Wd + (size_t)(kt * 16) * DIN + col0;
        cp16(&A[am0 * SA + ak],        Asrc + (size_t)am0 * DPAD + ak);
        cp16(&A[(am0 + 64) * SA + ak], Asrc + (size_t)(am0 + 64) * DPAD + ak);
        cp16(&B[bk0 * SB + bn],        Bsrc + (size_t)bk0 * DIN + bn);
        cp16(&B[(bk0 + 8) * SB + bn],  Bsrc + (size_t)(bk0 + 8) * DIN + bn);
    };

    float acc[2][8][4];
    #pragma unroll
    for (int mi = 0; mi < 2; ++mi)
        #pragma unroll
        for (int ni = 0; ni < 8; ++ni)
            #pragma unroll
            for (int q = 0; q < 4; ++q) acc[mi][ni][q] = 0.f;

    issue(0); CP_COMMIT;
    issue(1); CP_COMMIT;

    const int NT = DPAD / 16;  // 86
    for (int kt = 0; kt < NT; ++kt) {
        CP_WAIT1;
        __syncthreads();
        if (kt + 2 < NT) issue(kt + 2);
        CP_COMMIT;

        const float* A = sm + (kt % NSTAGE) * STG_G;
        const float* B = A + 128 * SA;
        #pragma unroll
        for (int ks = 0; ks < 2; ++ks) {
            const int kk = ks * 8;
            unsigned af[2][4], bf4[8][2];
            #pragma unroll
            for (int mi = 0; mi < 2; ++mi) {
                int r = wm * 32 + mi * 16 + grp;
                af[mi][0] = __float_as_uint(A[r * SA + kk + tig]);
                af[mi][1] = __float_as_uint(A[(r + 8) * SA + kk + tig]);
                af[mi][2] = __float_as_uint(A[r * SA + kk + tig + 4]);
                af[mi][3] = __float_as_uint(A[(r + 8) * SA + kk + tig + 4]);
            }
            #pragma unroll
            for (int ni = 0; ni < 8; ++ni) {
                int c = wn * 64 + ni * 8 + grp;
                bf4[ni][0] = __float_as_uint(B[(kk + tig) * SB + c]);
                bf4[ni][1] = __float_as_uint(B[(kk + tig + 4) * SB + c]);
            }
            #pragma unroll
            for (int mi = 0; mi < 2; ++mi)
                #pragma unroll
                for (int ni = 0; ni < 8; ++ni)
                    mma8(acc[mi][ni], af[mi], bf4[ni]);
        }
    }

    #pragma unroll
    for (int mi = 0; mi < 2; ++mi) {
        int r = row0 + wm * 32 + mi * 16 + grp;
        #pragma unroll
        for (int ni = 0; ni < 8; ++ni) {
            int c = col0 + wn * 64 + ni * 8 + tig * 2;
            float b0 = bd[c], b1 = bd[c + 1];
            float2 x0 = *(const float2*)&x[(size_t)r * DIN + c];
            float2 x1 = *(const float2*)&x[(size_t)(r + 8) * DIN + c];
            float2 v0 = {acc[mi][ni][0] + b0 + x0.x, acc[mi][ni][1] + b1 + x0.y};
            float2 v1 = {acc[mi][ni][2] + b0 + x1.x, acc[mi][ni][3] + b1 + x1.y};
            *(float2*)&y[(size_t)r * DIN + c]       = v0;
            *(float2*)&y[(size_t)(r + 8) * DIN + c] = v1;
        }
    }
}

// ---------------------------------------------------------------------------
extern "C" void kernel_launch(void* const* d_in, const int* in_sizes, int n_in,
                              void* d_out, int out_size)
{
    const float* x      = (const float*)d_in[0];
    const float* h_prev = (const float*)d_in[1];
    const float* c_prev = (const float*)d_in[2];
    const float* n_prev = (const float*)d_in[3];
    const float* m_prev = (const float*)d_in[4];
    const float* ln_w   = (const float*)d_in[5];
    const float* ln_b   = (const float*)d_in[6];
    const float* Wz = (const float*)d_in[7];
    const float* bz = (const float*)d_in[8];
    const float* Wi = (const float*)d_in[9];
    const float* bi = (const float*)d_in[10];
    const float* Wf = (const float*)d_in[11];
    const float* bf = (const float*)d_in[12];
    const float* Wo = (const float*)d_in[13];
    const float* bo = (const float*)d_in[14];
    const float* Rz  = (const float*)d_in[15];
    const float* rbz = (const float*)d_in[16];
    const float* Ri  = (const float*)d_in[17];
    const float* rbi = (const float*)d_in[18];
    const float* Rf  = (const float*)d_in[19];
    const float* rbf = (const float*)d_in[20];
    const float* Ro  = (const float*)d_in[21];
    const float* rbo = (const float*)d_in[22];
    const float* gn_w = (const float*)d_in[23];
    const float* gn_b = (const float*)d_in[24];
    const float* Wup  = (const float*)d_in[25];
    const float* bup  = (const float*)d_in[26];
    const float* Wdown = (const float*)d_in[27];
    const float* bdown = (const float*)d_in[28];

    float* out  = (float*)d_out;
    float* y_o  = out;
    float* ht_o = out + (size_t)PLANE;
    float* ct_o = out + (size_t)2 * PLANE;
    float* nt_o = out + (size_t)3 * PLANE;
    float* mt_o = out + (size_t)4 * PLANE;

    const int smG = NSTAGE * STG_G * 4;   // 56832
    const int smU = NSTAGE * STG_U * 4;   // 58368
    cudaFuncSetAttribute(gates_mma, cudaFuncAttributeMaxDynamicSharedMemorySize, smG);
    cudaFuncSetAttribute(upact_mma, cudaFuncAttributeMaxDynamicSharedMemorySize, smU);
    cudaFuncSetAttribute(down_mma,  cudaFuncAttributeMaxDynamicSharedMemorySize, smG);

    repack_wall<<<(DIN * GN + 255) / 256, 256>>>(Wz, Wi, Wf, Wo, bz, bi, bf, bo,
                                                 rbz, rbi, rbf, rbo);
    repack_rall<<<(HD * GN + 255) / 256, 256>>>(Rz, Ri, Rf, Ro);
    repack_wup<<<(DIN * NPAD + 255) / 256, 256>>>(Wup);
    repack_wd<<<(DPAD * DIN + 255) / 256, 256>>>(Wdown);
    round_h<<<(PLANE / 4 + 255) / 256, 256>>>(h_prev);

    ln_kernel<<<BSZ, 256>>>(x, ln_w, ln_b);

    gates_mma<<<dim3(GN / 128, BSZ / 128), 256, smG>>>();

    cell_kernel<<<BSZ * NH, 256>>>(c_prev, n_prev, m_prev, gn_w, gn_b,
                                   ht_o, ct_o, nt_o, mt_o);

    upact_mma<<<dim3(NPAD / 64, BSZ / 128), 256, smU>>>(bup);

    down_mma<<<dim3(DIN / 128, BSZ / 128), 256, smG>>>(x, bdown, y_o);
}

// round 7
// speedup vs baseline: 3.1012x; 1.0147x over previous
#include <cuda_runtime.h>
#include <math.h>
#include <stdint.h>

#define BSZ   8192
#define DIN   1024
#define DH    1024
#define HD    256
#define DP    1365
#define DPAD  1376
#define GN    4096
#define PLANE (BSZ*DH)

#define BM 128
#define SA 20                       // smem row stride (floats) for A and B tiles
#define STAGE_BYTES 20480           // A 128*20*4 + B 128*20*4
#define NSTAGE 4
#define SMEMSZ (NSTAGE*STAGE_BYTES) // 81920

#define G_KT 80
#define U_KT 64
#define D_KT 86
#define G_NT 32
#define U_NT 22
#define D_NT 8

// Scratch (static device globals — allocation-free rule)
__device__ float g_xnorm[(size_t)BSZ * DIN];
__device__ float g_hr[(size_t)BSZ * DH];
__device__ float g_gates[(size_t)BSZ * GN];
__device__ float g_htnorm[(size_t)BSZ * DH];
__device__ float g_act[(size_t)BSZ * DPAD];
__device__ float g_bias[GN];
// tile-linear B images: [tile][128 n-rows][16 k], tile = nt*KT + kt
__device__ float g_Bg[(size_t)G_NT * G_KT * 2048];
__device__ float g_Bup[(size_t)U_NT * U_KT * 2048];
__device__ float g_Bd[(size_t)D_NT * D_KT * 2048];

// ---------------- helpers ----------------
__device__ __forceinline__ float tf32r(float x) {
    unsigned u; asm("cvt.rna.tf32.f32 %0, %1;" : "=r"(u) : "f"(x));
    return __uint_as_float(u);
}
__device__ __forceinline__ float4 tf32r4(float4 v) {
    v.x = tf32r(v.x); v.y = tf32r(v.y); v.z = tf32r(v.z); v.w = tf32r(v.w);
    return v;
}
__device__ __forceinline__ void mma8(float* c, const unsigned* a, const unsigned* b) {
    asm volatile(
        "mma.sync.aligned.m16n8k8.row.col.f32.tf32.tf32.f32 "
        "{%0,%1,%2,%3}, {%4,%5,%6,%7}, {%8,%9}, {%0,%1,%2,%3};"
        : "+f"(c[0]), "+f"(c[1]), "+f"(c[2]), "+f"(c[3])
        : "r"(a[0]), "r"(a[1]), "r"(a[2]), "r"(a[3]), "r"(b[0]), "r"(b[1]));
}
__device__ __forceinline__ void cp16(uint32_t dst, const void* src) {
    asm volatile("cp.async.cg.shared.global [%0], [%1], 16;\n" :: "r"(dst), "l"(src));
}
#define CP_COMMIT asm volatile("cp.async.commit_group;\n" ::: "memory")
#define CP_WAIT(n) asm volatile("cp.async.wait_group %0;\n" :: "n"(n) : "memory")
#define LDSM4(R, addr) \
    asm volatile("ldmatrix.sync.aligned.m8n8.x4.shared.b16 {%0,%1,%2,%3}, [%4];" \
        : "=r"((R)[0]), "=r"((R)[1]), "=r"((R)[2]), "=r"((R)[3]) : "r"(addr))

// ---------------- repack kernels (tf32-rounded, tile-linear [n][k]) --------
__global__ __launch_bounds__(256) void repack_gb(
    const float* __restrict__ Wz, const float* __restrict__ Wi,
    const float* __restrict__ Wf, const float* __restrict__ Wo,
    const float* __restrict__ Rz, const float* __restrict__ Ri,
    const float* __restrict__ Rf, const float* __restrict__ Ro)
{
    size_t idx = (size_t)blockIdx.x * 256 + threadIdx.x;
    if (idx >= (size_t)G_NT * G_KT * 2048) return;
    int tile = (int)(idx >> 11), r = (int)(idx & 2047);
    int nloc = r >> 4, kloc = r & 15;
    int nt = tile / G_KT, kt = tile % G_KT;
    int n = nt * 128 + nloc, k = kt * 16 + kloc, gate = n >> 10;
    float v;
    if (k < 1024) {
        const float* W = (gate == 0) ? Wz : (gate == 1) ? Wi : (gate == 2) ? Wf : Wo;
        v = W[(size_t)k * DH + (n & 1023)];
    } else {
        const float* R = (gate == 0) ? Rz : (gate == 1) ? Ri : (gate == 2) ? Rf : Ro;
        v = R[((n >> 8) & 3) * 65536 + (k - 1024) * 256 + (n & 255)];
    }
    g_Bg[idx] = tf32r(v);
}

__global__ __launch_bounds__(256) void repack_ub(const float* __restrict__ Wup)
{
    size_t idx = (size_t)blockIdx.x * 256 + threadIdx.x;
    if (idx >= (size_t)U_NT * U_KT * 2048) return;
    int tile = (int)(idx >> 11), r = (int)(idx & 2047);
    int nloc = r >> 4, kloc = r & 15;
    int nt = tile / U_KT, kt = tile % U_KT;
    int half = nloc >> 6;                    // 0 = S rows, 1 = G rows
    int out = nt * 64 + (nloc & 63);
    int k = kt * 16 + kloc;
    float v = 0.f;
    if (out < DP) v = tf32r(Wup[(size_t)k * (2 * DP) + out + half * DP]);
    g_Bup[idx] = v;
}

__global__ __launch_bounds__(256) void repack_db(const float* __restrict__ Wd)
{
    size_t idx = (size_t)blockIdx.x * 256 + threadIdx.x;
    if (idx >= (size_t)D_NT * D_KT * 2048) return;
    int tile = (int)(idx >> 11), r = (int)(idx & 2047);
    int nloc = r >> 4, kloc = r & 15;
    int nt = tile / D_KT, kt = tile % D_KT;
    int n = nt * 128 + nloc, k = kt * 16 + kloc;
    g_Bd[idx] = (k < DP) ? tf32r(Wd[(size_t)k * DIN + n]) : 0.f;
}

__global__ __launch_bounds__(256) void make_bias(
    const float* __restrict__ bz, const float* __restrict__ bi,
    const float* __restrict__ bf, const float* __restrict__ bo,
    const float* __restrict__ rbz, const float* __restrict__ rbi,
    const float* __restrict__ rbf, const float* __restrict__ rbo)
{
    int c = blockIdx.x * 256 + threadIdx.x;
    if (c >= GN) return;
    int g = c >> 10, cl = c & 1023;
    const float* b  = (g == 0) ? bz  : (g == 1) ? bi  : (g == 2) ? bf  : bo;
    const float* rb = (g == 0) ? rbz : (g == 1) ? rbi : (g == 2) ? rbf : rbo;
    g_bias[c] = b[cl] + rb[cl];
}

__global__ __launch_bounds__(256) void round_h(const float* __restrict__ hp)
{
    int idx = blockIdx.x * 256 + threadIdx.x;
    if (idx >= PLANE / 4) return;
    ((float4*)g_hr)[idx] = tf32r4(((const float4*)hp)[idx]);
}

// ---------------- LayerNorm ----------------
__global__ __launch_bounds__(256) void ln_kernel(const float* __restrict__ x,
                                                 const float* __restrict__ w,
                                                 const float* __restrict__ b)
{
    int row = blockIdx.x, tid = threadIdx.x;
    float4 v = *(const float4*)(x + (size_t)row * DIN + tid * 4);
    float s = v.x + v.y + v.z + v.w;
    float ss = v.x*v.x + v.y*v.y + v.z*v.z + v.w*v.w;
    __shared__ float r0[8], r1[8];
    unsigned lane = tid & 31, wid = tid >> 5;
    #pragma unroll
    for (int o = 16; o; o >>= 1) {
        s += __shfl_down_sync(0xffffffffu, s, o);
        ss += __shfl_down_sync(0xffffffffu, ss, o);
    }
    if (!lane) { r0[wid] = s; r1[wid] = ss; }
    __syncthreads();
    float S = 0.f, SS = 0.f;
    #pragma unroll
    for (int i = 0; i < 8; ++i) { S += r0[i]; SS += r1[i]; }
    float mean = S * (1.f / DIN);
    float rstd = rsqrtf(SS * (1.f / DIN) - mean * mean + 1e-5f);
    float4 wv = *(const float4*)(w + tid * 4);
    float4 bv = *(const float4*)(b + tid * 4);
    float4 o4 = {(v.x-mean)*rstd*wv.x + bv.x, (v.y-mean)*rstd*wv.y + bv.y,
                 (v.z-mean)*rstd*wv.z + bv.z, (v.w-mean)*rstd*wv.w + bv.w};
    *(float4*)(g_xnorm + (size_t)row * DIN + tid * 4) = tf32r4(o4);
}

// ---------------- cell + GroupNorm ----------------
__global__ __launch_bounds__(256) void cell_kernel(
    const float* __restrict__ cp, const float* __restrict__ np,
    const float* __restrict__ mp,
    const float* __restrict__ gnw, const float* __restrict__ gnb,
    float* __restrict__ ht_o, float* __restrict__ ct_o,
    float* __restrict__ nt_o, float* __restrict__ mt_o)
{
    int bh = blockIdx.x, b = bh >> 2, h = bh & 3, d = threadIdx.x;
    size_t idx = (size_t)b * DH + h * 256 + d;
    size_t gb = (size_t)b * GN + h * 256 + d;
    float z = g_gates[gb], i_ = g_gates[gb+1024], f_ = g_gates[gb+2048], o_ = g_gates[gb+3072];
    float mpv = mp[idx], cpv = cp[idx], npv = np[idx];
    float zt = tanhf(z);
    float ot = 1.f / (1.f + expf(-o_));
    float fm = f_ + mpv;
    float mt = fmaxf(fm, i_);
    float it = expf(i_ - mt), ft = expf(fm - mt);
    float ct = ft * cpv + it * zt;
    float nt = ft * npv + it;
    float ht = ot * (ct / (nt + 1e-13f));
    ht_o[idx] = ht; ct_o[idx] = ct; nt_o[idx] = nt; mt_o[idx] = mt;
    float s = ht, ss = ht * ht;
    __shared__ float r0[8], r1[8];
    unsigned lane = d & 31, wid = d >> 5;
    #pragma unroll
    for (int o = 16; o; o >>= 1) {
        s += __shfl_down_sync(0xffffffffu, s, o);
        ss += __shfl_down_sync(0xffffffffu, ss, o);
    }
    if (!lane) { r0[wid] = s; r1[wid] = ss; }
    __syncthreads();
    float S = 0.f, SS = 0.f;
    #pragma unroll
    for (int i = 0; i < 8; ++i) { S += r0[i]; SS += r1[i]; }
    float mean = S * (1.f / 256.f);
    float rstd = rsqrtf(SS * (1.f / 256.f) - mean * mean + 1e-5f);
    int c = h * 256 + d;
    g_htnorm[idx] = tf32r((ht - mean) * rstd * gnw[c] + gnb[c]);
}

// ---------------- GEMM: mma.sync tf32 + ldmatrix fragments -----------------
// MODE 0 = gates (K=1280, bias epi), 1 = up+GeGLU (K=1024), 2 = down+residual
template<int MODE>
__global__ __launch_bounds__(256) void gemm_ls(const float* __restrict__ e0,
                                               const float* __restrict__ e1,
                                               float* __restrict__ outp)
{
    constexpr int KT  = (MODE == 0) ? G_KT : (MODE == 1) ? U_KT : D_KT;
    constexpr int AST = (MODE == 2) ? DPAD : DIN;

    extern __shared__ char smem[];
    const uint32_t sb = (uint32_t)__cvta_generic_to_shared(smem);

    const int tid = threadIdx.x, lane = tid & 31, wid = tid >> 5;
    const int wm = wid & 3, wn = wid >> 2;
    const int grp = lane >> 2, tig = lane & 3;
    const int nt = blockIdx.x, row0 = blockIdx.y * BM;

    // ldmatrix per-lane byte offsets within a stage
    const uint32_t aLane = ((uint32_t)((lane & 15) * SA + ((lane >> 4) << 2))) << 2;
    const uint32_t aOff0 = ((uint32_t)((wm * 32) * SA) << 2) + aLane;
    const uint32_t aOff1 = aOff0 + (16 * SA << 2);
    const int bRowLane = (lane & 7) + ((lane >> 4) << 3);
    const int bColOff  = ((lane >> 3) & 1) << 2;
    uint32_t bOff[4];
    #pragma unroll
    for (int p = 0; p < 4; ++p) {
        int ni = 2 * p;
        int nrow = (MODE == 1)
            ? ((ni < 4) ? wn * 32 + ni * 8 : 64 + wn * 32 + (ni - 4) * 8)
            : wn * 64 + ni * 8;
        bOff[p] = 10240u + (((uint32_t)((nrow + bRowLane) * SA + bColOff)) << 2);
    }

    const float* Abase = (MODE == 0) ? g_xnorm + (size_t)row0 * DIN
                       : (MODE == 1) ? g_htnorm + (size_t)row0 * DH
                                     : g_act + (size_t)row0 * DPAD;
    const float* Ahr = (MODE == 0)
        ? g_hr + (size_t)row0 * DH + ((nt >> 1) & 3) * HD : (const float*)0;
    const float* Bimg = (MODE == 0) ? g_Bg : (MODE == 1) ? g_Bup : g_Bd;

    auto loadTile = [&](int kt) {
        uint32_t stg = sb + (uint32_t)(kt & 3) * STAGE_BYTES;
        const float* Asrc = (MODE == 0 && kt >= 64)
            ? Ahr + (kt - 64) * 16 : Abase + kt * 16;
        // A tile: 128 rows x 16 floats = 512 float4 -> 2 per thread
        #pragma unroll
        for (int i = 0; i < 2; ++i) {
            int q = tid + i * 256;            // 0..511
            int r = q >> 2, c = q & 3;        // r 0..127
            cp16(stg + (uint32_t)(r * 80 + c * 16), Asrc + (size_t)r * AST + c * 4);
        }
        // B tile: 512 float4 -> 2 per thread
        const float4* Bsrc = (const float4*)(Bimg + ((size_t)nt * KT + kt) * 2048);
        #pragma unroll
        for (int i = 0; i < 2; ++i) {
            int q = tid + i * 256;
            cp16(stg + 10240u + (uint32_t)((q >> 2) * 80 + (q & 3) * 16), Bsrc + q);
        }
    };

    float acc[2][8][4];
    #pragma unroll
    for (int mi = 0; mi < 2; ++mi)
        #pragma unroll
        for (int ni = 0; ni < 8; ++ni)
            #pragma unroll
            for (int q = 0; q < 4; ++q) acc[mi][ni][q] = 0.f;

    loadTile(0); CP_COMMIT;
    loadTile(1); CP_COMMIT;
    loadTile(2); CP_COMMIT;

    for (int t = 0; t < KT; ++t) {
        // wait for tile t's group (allow later groups to stay pending)
        if (t <= KT - 3)      { CP_WAIT(2); }
        else if (t == KT - 2) { CP_WAIT(1); }
        else                  { CP_WAIT(0); }
        __syncthreads();                       // all reads of stage (t+3)&3 done
        if (t + 3 < KT) { loadTile(t + 3); CP_COMMIT; }

        uint32_t stg = sb + (uint32_t)(t & 3) * STAGE_BYTES;
        #pragma unroll
        for (int ks = 0; ks < 2; ++ks) {
            uint32_t kb = (uint32_t)(ks * 32);
            unsigned af[2][4], bf[8][2];
            LDSM4(af[0], stg + aOff0 + kb);
            LDSM4(af[1], stg + aOff1 + kb);
            LDSM4(&bf[0][0], stg + bOff[0] + kb);
            LDSM4(&bf[2][0], stg + bOff[1] + kb);
            LDSM4(&bf[4][0], stg + bOff[2] + kb);
            LDSM4(&bf[6][0], stg + bOff[3] + kb);
            #pragma unroll
            for (int mi = 0; mi < 2; ++mi)
                #pragma unroll
                for (int ni = 0; ni < 8; ++ni)
                    mma8(acc[mi][ni], af[mi], bf[ni]);
        }
    }
    __syncthreads();

    if (MODE != 1) {
        #pragma unroll
        for (int mi = 0; mi < 2; ++mi) {
            int r = row0 + wm * 32 + mi * 16 + grp;
            #pragma unroll
            for (int ni = 0; ni < 8; ++ni) {
                int c = nt * 128 + wn * 64 + ni * 8 + tig * 2;
                if (MODE == 0) {
                    float b0 = g_bias[c], b1 = g_bias[c + 1];
                    float2 v0 = {acc[mi][ni][0] + b0, acc[mi][ni][1] + b1};
                    float2 v1 = {acc[mi][ni][2] + b0, acc[mi][ni][3] + b1};
                    *(float2*)&g_gates[(size_t)r * GN + c]       = v0;
                    *(float2*)&g_gates[(size_t)(r + 8) * GN + c] = v1;
                } else {
                    float b0 = e1[c], b1 = e1[c + 1];
                    float2 x0 = *(const float2*)&e0[(size_t)r * DIN + c];
                    float2 x1 = *(const float2*)&e0[(size_t)(r + 8) * DIN + c];
                    float2 v0 = {acc[mi][ni][0] + b0 + x0.x, acc[mi][ni][1] + b1 + x0.y};
                    float2 v1 = {acc[mi][ni][2] + b0 + x1.x, acc[mi][ni][3] + b1 + x1.y};
                    *(float2*)&outp[(size_t)r * DIN + c]       = v0;
                    *(float2*)&outp[(size_t)(r + 8) * DIN + c] = v1;
                }
            }
        }
    } else {
        // acc[mi][j] = S, acc[mi][j+4] = G for the same output column
        #pragma unroll
        for (int mi = 0; mi < 2; ++mi) {
            int rb = row0 + wm * 32 + mi * 16 + grp;
            #pragma unroll
            for (int j = 0; j < 4; ++j) {
                int cc = nt * 64 + wn * 32 + j * 8 + tig * 2;
                #pragma unroll
                for (int h = 0; h < 2; ++h) {
                    int row = rb + h * 8;
                    #pragma unroll
                    for (int jj = 0; jj < 2; ++jj) {
                        int c2 = cc + jj;
                        if (c2 < DPAD) {
                            float v = 0.f;
                            if (c2 < DP) {
                                float sv = acc[mi][j][h * 2 + jj] + e0[c2];
                                float gv = acc[mi][j + 4][h * 2 + jj] + e0[c2 + DP];
                                float ge = 0.5f * gv * (1.f + erff(gv * 0.70710678118654752f));
                                v = tf32r(sv * ge);
                            }
                            g_act[(size_t)row * DPAD + c2] = v;
                        }
                    }
                }
            }
        }
    }
}

// ---------------- launch ----------------
extern "C" void kernel_launch(void* const* d_in, const int* in_sizes, int n_in,
                              void* d_out, int out_size)
{
    const float* x      = (const float*)d_in[0];
    const float* h_prev = (const float*)d_in[1];
    const float* c_prev = (const float*)d_in[2];
    const float* n_prev = (const float*)d_in[3];
    const float* m_prev = (const float*)d_in[4];
    const float* ln_w   = (const float*)d_in[5];
    const float* ln_b   = (const float*)d_in[6];
    const float* Wz = (const float*)d_in[7];
    const float* bz = (const float*)d_in[8];
    const float* Wi = (const float*)d_in[9];
    const float* bi = (const float*)d_in[10];
    const float* Wf = (const float*)d_in[11];
    const float* bf = (const float*)d_in[12];
    const float* Wo = (const float*)d_in[13];
    const float* bo = (const float*)d_in[14];
    const float* Rz  = (const float*)d_in[15];
    const float* rbz = (const float*)d_in[16];
    const float* Ri  = (const float*)d_in[17];
    const float* rbi = (const float*)d_in[18];
    const float* Rf  = (const float*)d_in[19];
    const float* rbf = (const float*)d_in[20];
    const float* Ro  = (const float*)d_in[21];
    const float* rbo = (const float*)d_in[22];
    const float* gn_w = (const float*)d_in[23];
    const float* gn_b = (const float*)d_in[24];
    const float* Wup  = (const float*)d_in[25];
    const float* bup  = (const float*)d_in[26];
    const float* Wdown = (const float*)d_in[27];
    const float* bdown = (const float*)d_in[28];

    float* out  = (float*)d_out;
    float* y_o  = out;
    float* ht_o = out + (size_t)PLANE;
    float* ct_o = out + (size_t)2 * PLANE;
    float* nt_o = out + (size_t)3 * PLANE;
    float* mt_o = out + (size_t)4 * PLANE;

    cudaFuncSetAttribute(gemm_ls<0>, cudaFuncAttributeMaxDynamicSharedMemorySize, SMEMSZ);
    cudaFuncSetAttribute(gemm_ls<1>, cudaFuncAttributeMaxDynamicSharedMemorySize, SMEMSZ);
    cudaFuncSetAttribute(gemm_ls<2>, cudaFuncAttributeMaxDynamicSharedMemorySize, SMEMSZ);

    repack_gb<<<(G_NT * G_KT * 2048 + 255) / 256, 256>>>(Wz, Wi, Wf, Wo, Rz, Ri, Rf, Ro);
    repack_ub<<<(U_NT * U_KT * 2048 + 255) / 256, 256>>>(Wup);
    repack_db<<<(D_NT * D_KT * 2048 + 255) / 256, 256>>>(Wdown);
    make_bias<<<GN / 256, 256>>>(bz, bi, bf, bo, rbz, rbi, rbf, rbo);
    round_h<<<(PLANE / 4 + 255) / 256, 256>>>(h_prev);

    ln_kernel<<<BSZ, 256>>>(x, ln_w, ln_b);

    gemm_ls<0><<<dim3(G_NT, BSZ / BM), 256, SMEMSZ>>>(nullptr, nullptr, nullptr);

    cell_kernel<<<BSZ * 4, 256>>>(c_prev, n_prev, m_prev, gn_w, gn_b,
                                  ht_o, ct_o, nt_o, mt_o);

    gemm_ls<1><<<dim3(U_NT, BSZ / BM), 256, SMEMSZ>>>(bup, nullptr, nullptr);

    gemm_ls<2><<<dim3(D_NT, BSZ / BM), 256, SMEMSZ>>>(x, bdown, y_o);
}